// round 10
// baseline (speedup 1.0000x reference)
#include <cuda_runtime.h>
#include <cstdint>
#include <mma.h>

using namespace nvcuda;

#define SEQ   2048
#define DIMSZ 4096
#define NHEAD 32
#define HDIM  128

// Scratch (device globals: allocation-free per harness rules)
__device__ float g_q[(size_t)SEQ * DIMSZ];
__device__ float g_k[(size_t)SEQ * DIMSZ];
__device__ float g_v[(size_t)SEQ * DIMSZ];
__device__ float g_o[(size_t)SEQ * DIMSZ];
__device__ float g_xt[(size_t)SEQ * DIMSZ];              // tf32-rounded x
__device__ float g_wt[(size_t)4 * DIMSZ * DIMSZ];        // tf32-rounded wq,wk,wv,wo

__device__ __forceinline__ float to_tf32(float x) { return wmma::__float_to_tf32(x); }

__device__ __forceinline__ void cp16(void* s, const float* g) {
    unsigned int sa = (unsigned int)__cvta_generic_to_shared(s);
    asm volatile("cp.async.cg.shared.global [%0], [%1], 16;" :: "r"(sa), "l"(g));
}
#define CP_COMMIT() asm volatile("cp.async.commit_group;")
#define CP_WAITG(n) asm volatile("cp.async.wait_group %0;" :: "n"(n))

// ---------------------------------------------------------------------------
// Fused tf32 pre-round of x (z=0) and the 4 weights (z=1..4).
// ---------------------------------------------------------------------------
#define W4 (DIMSZ * DIMSZ / 4)
#define X4 (SEQ * DIMSZ / 4)
__global__ void cvt_all(const float4* __restrict__ x,
                        const float4* __restrict__ w0, const float4* __restrict__ w1,
                        const float4* __restrict__ w2, const float4* __restrict__ w3,
                        float4* __restrict__ xt, float4* __restrict__ wt)
{
    int z = blockIdx.z;
    int i = blockIdx.x * blockDim.x + threadIdx.x;
    const float4* src;
    float4* dst;
    int n;
    if (z == 0)      { src = x;  dst = xt;          n = X4; }
    else if (z == 1) { src = w0; dst = wt;          n = W4; }
    else if (z == 2) { src = w1; dst = wt + W4;     n = W4; }
    else if (z == 3) { src = w2; dst = wt + 2 * W4; n = W4; }
    else             { src = w3; dst = wt + 3 * W4; n = W4; }
    if (i >= n) return;
    float4 v = src[i];
    dst[i] = make_float4(to_tf32(v.x), to_tf32(v.y), to_tf32(v.z), to_tf32(v.w));
}

// ---------------------------------------------------------------------------
// GEMM: C[2048,4096] = A[2048,4096] @ B[4096,4096], TF32 wmma.
// Block tile 128x128, BK=32, cp.async 3-stage pipeline. 256 thr = 8 warps.
// One kernel used for all 4 projections, launched SEQUENTIALLY so each
// GEMM's 96MB working set stays L2-resident (fused z=3 launch thrashed L2).
// ---------------------------------------------------------------------------
#define GM 2048
#define GN 4096
#define GK 4096
#define BK 32
#define NT (GK / BK)    // 128
#define STAGES 3
#define LDA 36
#define LDB 132
#define ASTAGE (128 * LDA)
#define BSTAGE (BK * LDB)
#define GEMM_SMEM_BYTES (STAGES * (ASTAGE + BSTAGE) * 4)

__device__ __forceinline__ void issue_stage(const float* __restrict__ A,
                                            const float* __restrict__ B,
                                            float* As, float* Bs,
                                            int bm, int bn, int kk, int tid)
{
#pragma unroll
    for (int i = 0; i < 4; i++) {
        int c = tid + i * 256;
        int r = c >> 3, k4 = (c & 7) << 2;
        cp16(&As[r * LDA + k4], A + (size_t)(bm + r) * GK + kk + k4);
    }
#pragma unroll
    for (int i = 0; i < 4; i++) {
        int c = tid + i * 256;
        int r = c >> 5, c4 = (c & 31) << 2;
        cp16(&Bs[r * LDB + c4], B + (size_t)(kk + r) * GN + bn + c4);
    }
}

__global__ __launch_bounds__(256, 2) void gemm_w(const float* __restrict__ A,
                                                 const float* __restrict__ B,
                                                 float* __restrict__ C,
                                                 int round_out)
{
    extern __shared__ float sm[];
    float* As = sm;
    float* Bs = sm + STAGES * ASTAGE;

    const int tid = threadIdx.x;
    const int w   = tid >> 5;
    const int bm  = blockIdx.x * 128;
    const int bn  = blockIdx.y * 128;
    const int wr  = (w >> 1) * 32;
    const int wc  = (w & 1) * 64;

    wmma::fragment<wmma::accumulator, 16, 16, 8, float> acc[2][4];
#pragma unroll
    for (int i = 0; i < 2; i++)
#pragma unroll
        for (int j = 0; j < 4; j++) wmma::fill_fragment(acc[i][j], 0.0f);

    issue_stage(A, B, As, Bs, bm, bn, 0, tid);
    CP_COMMIT();
    issue_stage(A, B, As + ASTAGE, Bs + BSTAGE, bm, bn, BK, tid);
    CP_COMMIT();

    for (int t = 0; t < NT; t++) {
        CP_WAITG(1);
        __syncthreads();

        int nk = t + 2;
        if (nk < NT) {
            int buf = nk % STAGES;
            issue_stage(A, B, As + buf * ASTAGE, Bs + buf * BSTAGE, bm, bn, nk * BK, tid);
        }
        CP_COMMIT();

        const float* Ac = As + (t % STAGES) * ASTAGE;
        const float* Bc = Bs + (t % STAGES) * BSTAGE;
#pragma unroll
        for (int ks = 0; ks < 4; ks++) {
            wmma::fragment<wmma::matrix_a, 16, 16, 8, wmma::precision::tf32, wmma::row_major> a[2];
            wmma::fragment<wmma::matrix_b, 16, 16, 8, wmma::precision::tf32, wmma::row_major> b[4];
#pragma unroll
            for (int i = 0; i < 2; i++)
                wmma::load_matrix_sync(a[i], &Ac[(wr + i * 16) * LDA + ks * 8], LDA);
#pragma unroll
            for (int j = 0; j < 4; j++)
                wmma::load_matrix_sync(b[j], &Bc[(ks * 8) * LDB + wc + j * 16], LDB);
#pragma unroll
            for (int i = 0; i < 2; i++)
#pragma unroll
                for (int j = 0; j < 4; j++)
                    wmma::mma_sync(acc[i][j], a[i], b[j], acc[i][j]);
        }
    }

    if (round_out) {
#pragma unroll
        for (int i = 0; i < 2; i++)
#pragma unroll
            for (int j = 0; j < 4; j++)
#pragma unroll
                for (int t = 0; t < acc[i][j].num_elements; t++)
                    acc[i][j].x[t] = to_tf32(acc[i][j].x[t]);
    }

#pragma unroll
    for (int i = 0; i < 2; i++)
#pragma unroll
        for (int j = 0; j < 4; j++)
            wmma::store_matrix_sync(C + (size_t)(bm + wr + i * 16) * GN + bn + wc + j * 16,
                                    acc[i][j], GN, wmma::mem_row_major);
}

// ---------------------------------------------------------------------------
// RoPE applied in-place to g_q and g_k; outputs tf32-rounded.
// ---------------------------------------------------------------------------
__global__ void rope_kernel(const float* __restrict__ fcos, const float* __restrict__ fsin)
{
    int idx = blockIdx.x * blockDim.x + threadIdx.x;
    if (idx >= SEQ * NHEAD * (HDIM / 2)) return;
    int i = idx & 63;
    int h = (idx >> 6) & (NHEAD - 1);
    int s = idx >> 11;
    float c  = fcos[s * 64 + i];
    float sn = fsin[s * 64 + i];
    size_t off = (size_t)s * DIMSZ + h * HDIM + 2 * i;
    float q0 = g_q[off], q1 = g_q[off + 1];
    g_q[off]     = to_tf32(q0 * c - q1 * sn);
    g_q[off + 1] = to_tf32(q0 * sn + q1 * c);
    float k0 = g_k[off], k1 = g_k[off + 1];
    g_k[off]     = to_tf32(k0 * c - k1 * sn);
    g_k[off + 1] = to_tf32(k0 * sn + k1 * c);
}

// ---------------------------------------------------------------------------
// Flash attention v5: register-resident O accumulator + double-buffered K/V
// + register-resident softmax state (m,l live in the 4 owner-threads of each
// row; only alpha crosses through smem for the PV warps).
// 2 CTAs/SM (111.4 KB).
// ---------------------------------------------------------------------------
#define BKT 32
#define LDQ 132
#define LDS_S 36
#define FLASH_SMEM_FLOATS (64 * LDQ + 4 * BKT * LDQ + 64 * LDS_S + 3 * 64)
#define FLASH_SMEM_BYTES (FLASH_SMEM_FLOATS * 4)

__global__ __launch_bounds__(256, 2) void flash_attn()
{
    extern __shared__ float smf[];
    float* Qs   = smf;                      // 64 x LDQ
    float* Ks   = Qs + 64 * LDQ;            // 2 x 32 x LDQ
    float* Vs   = Ks + 2 * BKT * LDQ;       // 2 x 32 x LDQ
    float* Ss   = Vs + 2 * BKT * LDQ;       // 64 x LDS_S
    float* lrow = Ss + 64 * LDS_S;          // 64 (epilogue only)
    float* arow = lrow + 64;                // 64 (per-iter alpha)

    const int qb   = (gridDim.x - 1) - blockIdx.x;   // long blocks first
    const int h    = blockIdx.y;
    const int tid  = threadIdx.x;
    const int w    = tid >> 5;
    const int lane = tid & 31;
    const float scale = 0.08838834764831845f;  // 1/sqrt(128)

    const float* Qg = g_q + (size_t)qb * 64 * DIMSZ + h * HDIM;
    const float* Kh = g_k + (size_t)h * HDIM;
    const float* Vh = g_v + (size_t)h * HDIM;

    // O ownership (PV warp grid 2x4)
    const int owr = (w >> 2) * 32;
    const int owc = (w & 3) * 32;
    wmma::fragment<wmma::accumulator, 16, 16, 8, float> oacc[2][2];
#pragma unroll
    for (int i = 0; i < 2; i++)
#pragma unroll
        for (int j = 0; j < 2; j++) wmma::fill_fragment(oacc[i][j], 0.0f);

    // Register softmax state: thread group (r = tid>>2) owns row r.
    const int srow = tid >> 2;
    const int ssub = tid & 3;
    float m_state = -1e30f;
    float l_state = 0.0f;

    // Prologue: Q + K0/V0 as one group.
#pragma unroll
    for (int i = 0; i < 8; i++) {
        int idx = tid + i * 256;
        int r = idx >> 5, d4 = (idx & 31) << 2;
        cp16(&Qs[r * LDQ + d4], Qg + (size_t)r * DIMSZ + d4);
    }
#pragma unroll
    for (int i = 0; i < 4; i++) {
        int idx = tid + i * 256;
        int r = idx >> 5, d4 = (idx & 31) << 2;
        cp16(&Ks[r * LDQ + d4], Kh + (size_t)r * DIMSZ + d4);
        cp16(&Vs[r * LDQ + d4], Vh + (size_t)r * DIMSZ + d4);
    }
    CP_COMMIT();

    const int ntiles = 2 * qb + 2;

    for (int kt = 0; kt < ntiles; kt++) {
        const int buf = kt & 1;

        if (kt + 1 < ntiles) {
            float* Kn = Ks + (buf ^ 1) * BKT * LDQ;
            float* Vn = Vs + (buf ^ 1) * BKT * LDQ;
            const float* Kg = Kh + (size_t)(kt + 1) * BKT * DIMSZ;
            const float* Vg = Vh + (size_t)(kt + 1) * BKT * DIMSZ;
#pragma unroll
            for (int i = 0; i < 4; i++) {
                int idx = tid + i * 256;
                int r = idx >> 5, d4 = (idx & 31) << 2;
                cp16(&Kn[r * LDQ + d4], Kg + (size_t)r * DIMSZ + d4);
                cp16(&Vn[r * LDQ + d4], Vg + (size_t)r * DIMSZ + d4);
            }
            CP_COMMIT();
            CP_WAITG(1);
        } else {
            CP_WAITG(0);
        }
        __syncthreads();    // current K/V (+Q first iter) visible

        const float* Kc = Ks + buf * BKT * LDQ;
        const float* Vc = Vs + buf * BKT * LDQ;

        // S = scale * Q @ K^T : warp grid 4x2, each warp 16x16
        {
            const int wr = (w >> 1) * 16;
            const int wc = (w & 1) * 16;
            wmma::fragment<wmma::accumulator, 16, 16, 8, float> c;
            wmma::fill_fragment(c, 0.0f);
#pragma unroll
            for (int ks = 0; ks < 16; ks++) {
                wmma::fragment<wmma::matrix_a, 16, 16, 8, wmma::precision::tf32, wmma::row_major> a;
                wmma::fragment<wmma::matrix_b, 16, 16, 8, wmma::precision::tf32, wmma::col_major> b;
                wmma::load_matrix_sync(a, &Qs[wr * LDQ + ks * 8], LDQ);
                wmma::load_matrix_sync(b, &Kc[wc * LDQ + ks * 8], LDQ);
                wmma::mma_sync(c, a, b, c);
            }
#pragma unroll
            for (int t = 0; t < c.num_elements; t++) c.x[t] *= scale;
            wmma::store_matrix_sync(&Ss[wr * LDS_S + wc], c, LDS_S, wmma::mem_row_major);
        }
        __syncthreads();    // S visible

        // Online softmax: state in registers; alpha -> smem for PV warps.
        {
            int lim = qb * 64 + srow - kt * BKT;
            int smax = lim + 1;
            if (smax > BKT) smax = BKT;
            if (smax < 0)   smax = 0;
            float mloc = -1e30f;
            int c0 = ssub * 8;
#pragma unroll
            for (int c = 0; c < 8; c++) {
                int cc = c0 + c;
                if (cc < smax) mloc = fmaxf(mloc, Ss[srow * LDS_S + cc]);
            }
#pragma unroll
            for (int o = 1; o < 4; o <<= 1)
                mloc = fmaxf(mloc, __shfl_xor_sync(0xffffffffu, mloc, o));
            float mn = fmaxf(m_state, mloc);
            float alpha = __expf(m_state - mn);
            float lsum = 0.0f;
#pragma unroll
            for (int c = 0; c < 8; c++) {
                int cc = c0 + c;
                float p = (cc < smax) ? __expf(Ss[srow * LDS_S + cc] - mn) : 0.0f;
                p = to_tf32(p);
                Ss[srow * LDS_S + cc] = p;
                lsum += p;
            }
#pragma unroll
            for (int o = 1; o < 4; o <<= 1)
                lsum += __shfl_xor_sync(0xffffffffu, lsum, o);
            l_state = l_state * alpha + lsum;
            m_state = mn;
            if (ssub == 0) arow[srow] = alpha;
        }
        __syncthreads();    // P + arow visible

        // Rescale O accumulator in registers (row map: lane/4, +8 for e%4>=2)
        {
            const int r0 = lane >> 2;
#pragma unroll
            for (int i = 0; i < 2; i++) {
                float a0 = arow[owr + i * 16 + r0];
                float a1 = arow[owr + i * 16 + r0 + 8];
#pragma unroll
                for (int j = 0; j < 2; j++)
#pragma unroll
                    for (int e = 0; e < 8; e++)
                        oacc[i][j].x[e] *= ((e & 3) >= 2) ? a1 : a0;
            }
        }

        // O += P @ V : warp grid 2x4, each warp 32x32, 4 k-steps
        {
#pragma unroll
            for (int ks = 0; ks < 4; ks++) {
                wmma::fragment<wmma::matrix_a, 16, 16, 8, wmma::precision::tf32, wmma::row_major> a[2];
                wmma::fragment<wmma::matrix_b, 16, 16, 8, wmma::precision::tf32, wmma::row_major> b[2];
#pragma unroll
                for (int i = 0; i < 2; i++)
                    wmma::load_matrix_sync(a[i], &Ss[(owr + i * 16) * LDS_S + ks * 8], LDS_S);
#pragma unroll
                for (int j = 0; j < 2; j++)
                    wmma::load_matrix_sync(b[j], &Vc[(ks * 8) * LDQ + owc + j * 16], LDQ);
#pragma unroll
                for (int i = 0; i < 2; i++)
#pragma unroll
                    for (int j = 0; j < 2; j++)
                        wmma::mma_sync(oacc[i][j], a[i], b[j], oacc[i][j]);
            }
        }
        __syncthreads();    // Ss/Vc/Kc readers done
    }

    // Publish l for epilogue, then normalize in registers and store.
    if (ssub == 0) lrow[srow] = l_state;
    __syncthreads();

    float* Og = g_o + (size_t)qb * 64 * DIMSZ + h * HDIM;
    {
        const int r0 = lane >> 2;
#pragma unroll
        for (int i = 0; i < 2; i++) {
            float inv0 = 1.0f / lrow[owr + i * 16 + r0];
            float inv1 = 1.0f / lrow[owr + i * 16 + r0 + 8];
#pragma unroll
            for (int j = 0; j < 2; j++) {
#pragma unroll
                for (int e = 0; e < 8; e++)
                    oacc[i][j].x[e] = to_tf32(oacc[i][j].x[e] *
                                              (((e & 3) >= 2) ? inv1 : inv0));
                wmma::store_matrix_sync(Og + (size_t)(owr + i * 16) * DIMSZ + owc + j * 16,
                                        oacc[i][j], DIMSZ, wmma::mem_row_major);
            }
        }
    }
}

// ---------------------------------------------------------------------------
extern "C" void kernel_launch(void* const* d_in, const int* in_sizes, int n_in,
                              void* d_out, int out_size)
{
    const float* x  = (const float*)d_in[0];
    const float* wq = (const float*)d_in[1];
    const float* wk = (const float*)d_in[2];
    const float* wv = (const float*)d_in[3];
    const float* wo = (const float*)d_in[4];
    const float* fc = (const float*)d_in[5];
    const float* fs = (const float*)d_in[6];
    float* out = (float*)d_out;

    float *xt, *wt, *q, *k, *v, *o;
    cudaGetSymbolAddress((void**)&xt, g_xt);
    cudaGetSymbolAddress((void**)&wt, g_wt);
    cudaGetSymbolAddress((void**)&q,  g_q);
    cudaGetSymbolAddress((void**)&k,  g_k);
    cudaGetSymbolAddress((void**)&v,  g_v);
    cudaGetSymbolAddress((void**)&o,  g_o);

    cudaFuncSetAttribute(gemm_w, cudaFuncAttributeMaxDynamicSharedMemorySize,
                         GEMM_SMEM_BYTES);
    cudaFuncSetAttribute(flash_attn, cudaFuncAttributeMaxDynamicSharedMemorySize,
                         FLASH_SMEM_BYTES);

    // 1: fused tf32 pre-round (x + 4 weights)
    dim3 cgrid((W4 + 255) / 256, 1, 5);
    cvt_all<<<cgrid, 256>>>((const float4*)x, (const float4*)wq, (const float4*)wk,
                            (const float4*)wv, (const float4*)wo,
                            (float4*)xt, (float4*)wt);

    // 2-4: Q/K/V projections SEQUENTIALLY (L2 locality; #4 = profiled GEMM)
    dim3 ggrid(GM / 128, GN / 128);
    gemm_w<<<ggrid, 256, GEMM_SMEM_BYTES>>>(xt, wt + (size_t)0 * DIMSZ * DIMSZ, q, 1);
    gemm_w<<<ggrid, 256, GEMM_SMEM_BYTES>>>(xt, wt + (size_t)1 * DIMSZ * DIMSZ, k, 1);
    gemm_w<<<ggrid, 256, GEMM_SMEM_BYTES>>>(xt, wt + (size_t)2 * DIMSZ * DIMSZ, v, 1);

    // 5: RoPE
    int npairs = SEQ * NHEAD * (HDIM / 2);
    rope_kernel<<<(npairs + 255) / 256, 256>>>(fc, fs);

    // 6: flash attention
    flash_attn<<<dim3(SEQ / 64, NHEAD), 256, FLASH_SMEM_BYTES>>>();

    // 7: output projection
    gemm_w<<<ggrid, 256, GEMM_SMEM_BYTES>>>(o, wt + (size_t)3 * DIMSZ * DIMSZ, out, 0);
}

// round 11
// speedup vs baseline: 1.0613x; 1.0613x over previous
#include <cuda_runtime.h>
#include <cstdint>
#include <mma.h>

using namespace nvcuda;

#define SEQ   2048
#define DIMSZ 4096
#define NHEAD 32
#define HDIM  128

// Scratch (device globals: allocation-free per harness rules)
__device__ float g_q[(size_t)SEQ * DIMSZ];
__device__ float g_k[(size_t)SEQ * DIMSZ];
__device__ float g_v[(size_t)SEQ * DIMSZ];
__device__ float g_o[(size_t)SEQ * DIMSZ];
__device__ float g_xt[(size_t)SEQ * DIMSZ];              // tf32-rounded x
__device__ float g_wt[(size_t)4 * DIMSZ * DIMSZ];        // tf32-rounded wq,wk,wv,wo

__device__ __forceinline__ float to_tf32(float x) { return wmma::__float_to_tf32(x); }

__device__ __forceinline__ void cp16(void* s, const float* g) {
    unsigned int sa = (unsigned int)__cvta_generic_to_shared(s);
    asm volatile("cp.async.cg.shared.global [%0], [%1], 16;" :: "r"(sa), "l"(g));
}
#define CP_COMMIT() asm volatile("cp.async.commit_group;")
#define CP_WAITG(n) asm volatile("cp.async.wait_group %0;" :: "n"(n))

// ---------------------------------------------------------------------------
// Fused tf32 pre-round of x (z=0) and the 4 weights (z=1..4).
// ---------------------------------------------------------------------------
#define W4 (DIMSZ * DIMSZ / 4)
#define X4 (SEQ * DIMSZ / 4)
__global__ void cvt_all(const float4* __restrict__ x,
                        const float4* __restrict__ w0, const float4* __restrict__ w1,
                        const float4* __restrict__ w2, const float4* __restrict__ w3,
                        float4* __restrict__ xt, float4* __restrict__ wt)
{
    int z = blockIdx.z;
    int i = blockIdx.x * blockDim.x + threadIdx.x;
    const float4* src;
    float4* dst;
    int n;
    if (z == 0)      { src = x;  dst = xt;          n = X4; }
    else if (z == 1) { src = w0; dst = wt;          n = W4; }
    else if (z == 2) { src = w1; dst = wt + W4;     n = W4; }
    else if (z == 3) { src = w2; dst = wt + 2 * W4; n = W4; }
    else             { src = w3; dst = wt + 3 * W4; n = W4; }
    if (i >= n) return;
    float4 v = src[i];
    dst[i] = make_float4(to_tf32(v.x), to_tf32(v.y), to_tf32(v.z), to_tf32(v.w));
}

// ---------------------------------------------------------------------------
// GEMM: C[2048,4096] = A[2048,4096] @ B[4096,4096], TF32 wmma.
// Block tile 128x128, BK=32, cp.async 3-stage pipeline. 256 thr = 8 warps.
// QKV fused in one z=3 launch (1536 CTAs -> good wave packing; split
// launches regressed +286us from per-GEMM wave tails).
// ---------------------------------------------------------------------------
#define GM 2048
#define GN 4096
#define GK 4096
#define BK 32
#define NT (GK / BK)    // 128
#define STAGES 3
#define LDA 36
#define LDB 132
#define ASTAGE (128 * LDA)
#define BSTAGE (BK * LDB)
#define GEMM_SMEM_BYTES (STAGES * (ASTAGE + BSTAGE) * 4)

__device__ __forceinline__ void issue_stage(const float* __restrict__ A,
                                            const float* __restrict__ B,
                                            float* As, float* Bs,
                                            int bm, int bn, int kk, int tid)
{
#pragma unroll
    for (int i = 0; i < 4; i++) {
        int c = tid + i * 256;
        int r = c >> 3, k4 = (c & 7) << 2;
        cp16(&As[r * LDA + k4], A + (size_t)(bm + r) * GK + kk + k4);
    }
#pragma unroll
    for (int i = 0; i < 4; i++) {
        int c = tid + i * 256;
        int r = c >> 5, c4 = (c & 31) << 2;
        cp16(&Bs[r * LDB + c4], B + (size_t)(kk + r) * GN + bn + c4);
    }
}

__device__ __forceinline__ void gemm_core(const float* __restrict__ A,
                                          const float* __restrict__ B,
                                          float* __restrict__ C,
                                          float* sm, bool round_out)
{
    float* As = sm;
    float* Bs = sm + STAGES * ASTAGE;

    const int tid = threadIdx.x;
    const int w   = tid >> 5;
    const int bm  = blockIdx.x * 128;
    const int bn  = blockIdx.y * 128;
    const int wr  = (w >> 1) * 32;
    const int wc  = (w & 1) * 64;

    wmma::fragment<wmma::accumulator, 16, 16, 8, float> acc[2][4];
#pragma unroll
    for (int i = 0; i < 2; i++)
#pragma unroll
        for (int j = 0; j < 4; j++) wmma::fill_fragment(acc[i][j], 0.0f);

    issue_stage(A, B, As, Bs, bm, bn, 0, tid);
    CP_COMMIT();
    issue_stage(A, B, As + ASTAGE, Bs + BSTAGE, bm, bn, BK, tid);
    CP_COMMIT();

    for (int t = 0; t < NT; t++) {
        CP_WAITG(1);
        __syncthreads();

        int nk = t + 2;
        if (nk < NT) {
            int buf = nk % STAGES;
            issue_stage(A, B, As + buf * ASTAGE, Bs + buf * BSTAGE, bm, bn, nk * BK, tid);
        }
        CP_COMMIT();

        const float* Ac = As + (t % STAGES) * ASTAGE;
        const float* Bc = Bs + (t % STAGES) * BSTAGE;
#pragma unroll
        for (int ks = 0; ks < 4; ks++) {
            wmma::fragment<wmma::matrix_a, 16, 16, 8, wmma::precision::tf32, wmma::row_major> a[2];
            wmma::fragment<wmma::matrix_b, 16, 16, 8, wmma::precision::tf32, wmma::row_major> b[4];
#pragma unroll
            for (int i = 0; i < 2; i++)
                wmma::load_matrix_sync(a[i], &Ac[(wr + i * 16) * LDA + ks * 8], LDA);
#pragma unroll
            for (int j = 0; j < 4; j++)
                wmma::load_matrix_sync(b[j], &Bc[(ks * 8) * LDB + wc + j * 16], LDB);
#pragma unroll
            for (int i = 0; i < 2; i++)
#pragma unroll
                for (int j = 0; j < 4; j++)
                    wmma::mma_sync(acc[i][j], a[i], b[j], acc[i][j]);
        }
    }

    if (round_out) {
#pragma unroll
        for (int i = 0; i < 2; i++)
#pragma unroll
            for (int j = 0; j < 4; j++)
#pragma unroll
                for (int t = 0; t < acc[i][j].num_elements; t++)
                    acc[i][j].x[t] = to_tf32(acc[i][j].x[t]);
    }

#pragma unroll
    for (int i = 0; i < 2; i++)
#pragma unroll
        for (int j = 0; j < 4; j++)
            wmma::store_matrix_sync(C + (size_t)(bm + wr + i * 16) * GN + bn + wc + j * 16,
                                    acc[i][j], GN, wmma::mem_row_major);
}

__global__ __launch_bounds__(256, 2) void gemm_qkv(const float* __restrict__ x)
{
    extern __shared__ float sm[];
    const float* B = g_wt + (size_t)blockIdx.z * DIMSZ * DIMSZ;
    float* C = (blockIdx.z == 0) ? g_q : (blockIdx.z == 1) ? g_k : g_v;
    gemm_core(x, B, C, sm, true);   // round Q/K/V to tf32 (feeds rope & flash)
}

__global__ __launch_bounds__(256, 2) void gemm_out(const float* __restrict__ A,
                                                   float* __restrict__ C)
{
    extern __shared__ float sm[];
    gemm_core(A, g_wt + (size_t)3 * DIMSZ * DIMSZ, C, sm, false);
}

// ---------------------------------------------------------------------------
// RoPE applied in-place to g_q and g_k; outputs tf32-rounded.
// ---------------------------------------------------------------------------
__global__ void rope_kernel(const float* __restrict__ fcos, const float* __restrict__ fsin)
{
    int idx = blockIdx.x * blockDim.x + threadIdx.x;
    if (idx >= SEQ * NHEAD * (HDIM / 2)) return;
    int i = idx & 63;
    int h = (idx >> 6) & (NHEAD - 1);
    int s = idx >> 11;
    float c  = fcos[s * 64 + i];
    float sn = fsin[s * 64 + i];
    size_t off = (size_t)s * DIMSZ + h * HDIM + 2 * i;
    float q0 = g_q[off], q1 = g_q[off + 1];
    g_q[off]     = to_tf32(q0 * c - q1 * sn);
    g_q[off + 1] = to_tf32(q0 * sn + q1 * c);
    float k0 = g_k[off], k1 = g_k[off + 1];
    g_k[off]     = to_tf32(k0 * c - k1 * sn);
    g_k[off + 1] = to_tf32(k0 * sn + k1 * c);
}

// ---------------------------------------------------------------------------
// Flash attention v5: register-resident O accumulator + double-buffered K/V
// + register-resident softmax state. 2 CTAs/SM (111.4 KB).
// ---------------------------------------------------------------------------
#define BKT 32
#define LDQ 132
#define LDS_S 36
#define FLASH_SMEM_FLOATS (64 * LDQ + 4 * BKT * LDQ + 64 * LDS_S + 3 * 64)
#define FLASH_SMEM_BYTES (FLASH_SMEM_FLOATS * 4)

__global__ __launch_bounds__(256, 2) void flash_attn()
{
    extern __shared__ float smf[];
    float* Qs   = smf;                      // 64 x LDQ
    float* Ks   = Qs + 64 * LDQ;            // 2 x 32 x LDQ
    float* Vs   = Ks + 2 * BKT * LDQ;       // 2 x 32 x LDQ
    float* Ss   = Vs + 2 * BKT * LDQ;       // 64 x LDS_S
    float* lrow = Ss + 64 * LDS_S;          // 64 (epilogue only)
    float* arow = lrow + 64;                // 64 (per-iter alpha)

    const int qb   = (gridDim.x - 1) - blockIdx.x;   // long blocks first
    const int h    = blockIdx.y;
    const int tid  = threadIdx.x;
    const int w    = tid >> 5;
    const int lane = tid & 31;
    const float scale = 0.08838834764831845f;  // 1/sqrt(128)

    const float* Qg = g_q + (size_t)qb * 64 * DIMSZ + h * HDIM;
    const float* Kh = g_k + (size_t)h * HDIM;
    const float* Vh = g_v + (size_t)h * HDIM;

    // O ownership (PV warp grid 2x4)
    const int owr = (w >> 2) * 32;
    const int owc = (w & 3) * 32;
    wmma::fragment<wmma::accumulator, 16, 16, 8, float> oacc[2][2];
#pragma unroll
    for (int i = 0; i < 2; i++)
#pragma unroll
        for (int j = 0; j < 2; j++) wmma::fill_fragment(oacc[i][j], 0.0f);

    // Register softmax state: thread group (r = tid>>2) owns row r.
    const int srow = tid >> 2;
    const int ssub = tid & 3;
    float m_state = -1e30f;
    float l_state = 0.0f;

    // Prologue: Q + K0/V0 as one group.
#pragma unroll
    for (int i = 0; i < 8; i++) {
        int idx = tid + i * 256;
        int r = idx >> 5, d4 = (idx & 31) << 2;
        cp16(&Qs[r * LDQ + d4], Qg + (size_t)r * DIMSZ + d4);
    }
#pragma unroll
    for (int i = 0; i < 4; i++) {
        int idx = tid + i * 256;
        int r = idx >> 5, d4 = (idx & 31) << 2;
        cp16(&Ks[r * LDQ + d4], Kh + (size_t)r * DIMSZ + d4);
        cp16(&Vs[r * LDQ + d4], Vh + (size_t)r * DIMSZ + d4);
    }
    CP_COMMIT();

    const int ntiles = 2 * qb + 2;

    for (int kt = 0; kt < ntiles; kt++) {
        const int buf = kt & 1;

        if (kt + 1 < ntiles) {
            float* Kn = Ks + (buf ^ 1) * BKT * LDQ;
            float* Vn = Vs + (buf ^ 1) * BKT * LDQ;
            const float* Kg = Kh + (size_t)(kt + 1) * BKT * DIMSZ;
            const float* Vg = Vh + (size_t)(kt + 1) * BKT * DIMSZ;
#pragma unroll
            for (int i = 0; i < 4; i++) {
                int idx = tid + i * 256;
                int r = idx >> 5, d4 = (idx & 31) << 2;
                cp16(&Kn[r * LDQ + d4], Kg + (size_t)r * DIMSZ + d4);
                cp16(&Vn[r * LDQ + d4], Vg + (size_t)r * DIMSZ + d4);
            }
            CP_COMMIT();
            CP_WAITG(1);
        } else {
            CP_WAITG(0);
        }
        __syncthreads();    // current K/V (+Q first iter) visible

        const float* Kc = Ks + buf * BKT * LDQ;
        const float* Vc = Vs + buf * BKT * LDQ;

        // S = scale * Q @ K^T : warp grid 4x2, each warp 16x16
        {
            const int wr = (w >> 1) * 16;
            const int wc = (w & 1) * 16;
            wmma::fragment<wmma::accumulator, 16, 16, 8, float> c;
            wmma::fill_fragment(c, 0.0f);
#pragma unroll
            for (int ks = 0; ks < 16; ks++) {
                wmma::fragment<wmma::matrix_a, 16, 16, 8, wmma::precision::tf32, wmma::row_major> a;
                wmma::fragment<wmma::matrix_b, 16, 16, 8, wmma::precision::tf32, wmma::col_major> b;
                wmma::load_matrix_sync(a, &Qs[wr * LDQ + ks * 8], LDQ);
                wmma::load_matrix_sync(b, &Kc[wc * LDQ + ks * 8], LDQ);
                wmma::mma_sync(c, a, b, c);
            }
#pragma unroll
            for (int t = 0; t < c.num_elements; t++) c.x[t] *= scale;
            wmma::store_matrix_sync(&Ss[wr * LDS_S + wc], c, LDS_S, wmma::mem_row_major);
        }
        __syncthreads();    // S visible

        // Online softmax: state in registers; alpha -> smem for PV warps.
        {
            int lim = qb * 64 + srow - kt * BKT;
            int smax = lim + 1;
            if (smax > BKT) smax = BKT;
            if (smax < 0)   smax = 0;
            float mloc = -1e30f;
            int c0 = ssub * 8;
#pragma unroll
            for (int c = 0; c < 8; c++) {
                int cc = c0 + c;
                if (cc < smax) mloc = fmaxf(mloc, Ss[srow * LDS_S + cc]);
            }
#pragma unroll
            for (int o = 1; o < 4; o <<= 1)
                mloc = fmaxf(mloc, __shfl_xor_sync(0xffffffffu, mloc, o));
            float mn = fmaxf(m_state, mloc);
            float alpha = __expf(m_state - mn);
            float lsum = 0.0f;
#pragma unroll
            for (int c = 0; c < 8; c++) {
                int cc = c0 + c;
                float p = (cc < smax) ? __expf(Ss[srow * LDS_S + cc] - mn) : 0.0f;
                p = to_tf32(p);
                Ss[srow * LDS_S + cc] = p;
                lsum += p;
            }
#pragma unroll
            for (int o = 1; o < 4; o <<= 1)
                lsum += __shfl_xor_sync(0xffffffffu, lsum, o);
            l_state = l_state * alpha + lsum;
            m_state = mn;
            if (ssub == 0) arow[srow] = alpha;
        }
        __syncthreads();    // P + arow visible

        // Rescale O accumulator in registers (row map: lane/4, +8 for e%4>=2)
        {
            const int r0 = lane >> 2;
#pragma unroll
            for (int i = 0; i < 2; i++) {
                float a0 = arow[owr + i * 16 + r0];
                float a1 = arow[owr + i * 16 + r0 + 8];
#pragma unroll
                for (int j = 0; j < 2; j++)
#pragma unroll
                    for (int e = 0; e < 8; e++)
                        oacc[i][j].x[e] *= ((e & 3) >= 2) ? a1 : a0;
            }
        }

        // O += P @ V : warp grid 2x4, each warp 32x32, 4 k-steps
        {
#pragma unroll
            for (int ks = 0; ks < 4; ks++) {
                wmma::fragment<wmma::matrix_a, 16, 16, 8, wmma::precision::tf32, wmma::row_major> a[2];
                wmma::fragment<wmma::matrix_b, 16, 16, 8, wmma::precision::tf32, wmma::row_major> b[2];
#pragma unroll
                for (int i = 0; i < 2; i++)
                    wmma::load_matrix_sync(a[i], &Ss[(owr + i * 16) * LDS_S + ks * 8], LDS_S);
#pragma unroll
                for (int j = 0; j < 2; j++)
                    wmma::load_matrix_sync(b[j], &Vc[(ks * 8) * LDQ + owc + j * 16], LDQ);
#pragma unroll
                for (int i = 0; i < 2; i++)
#pragma unroll
                    for (int j = 0; j < 2; j++)
                        wmma::mma_sync(oacc[i][j], a[i], b[j], oacc[i][j]);
            }
        }
        __syncthreads();    // Ss/Vc/Kc readers done
    }

    // Publish l for epilogue, then normalize in registers and store.
    if (ssub == 0) lrow[srow] = l_state;
    __syncthreads();

    float* Og = g_o + (size_t)qb * 64 * DIMSZ + h * HDIM;
    {
        const int r0 = lane >> 2;
#pragma unroll
        for (int i = 0; i < 2; i++) {
            float inv0 = 1.0f / lrow[owr + i * 16 + r0];
            float inv1 = 1.0f / lrow[owr + i * 16 + r0 + 8];
#pragma unroll
            for (int j = 0; j < 2; j++) {
#pragma unroll
                for (int e = 0; e < 8; e++)
                    oacc[i][j].x[e] = to_tf32(oacc[i][j].x[e] *
                                              (((e & 3) >= 2) ? inv1 : inv0));
                wmma::store_matrix_sync(Og + (size_t)(owr + i * 16) * DIMSZ + owc + j * 16,
                                        oacc[i][j], DIMSZ, wmma::mem_row_major);
            }
        }
    }
}

// ---------------------------------------------------------------------------
extern "C" void kernel_launch(void* const* d_in, const int* in_sizes, int n_in,
                              void* d_out, int out_size)
{
    const float* x  = (const float*)d_in[0];
    const float* wq = (const float*)d_in[1];
    const float* wk = (const float*)d_in[2];
    const float* wv = (const float*)d_in[3];
    const float* wo = (const float*)d_in[4];
    const float* fc = (const float*)d_in[5];
    const float* fs = (const float*)d_in[6];
    float* out = (float*)d_out;

    float *xt, *wt, *o;
    cudaGetSymbolAddress((void**)&xt, g_xt);
    cudaGetSymbolAddress((void**)&wt, g_wt);
    cudaGetSymbolAddress((void**)&o,  g_o);

    cudaFuncSetAttribute(gemm_qkv, cudaFuncAttributeMaxDynamicSharedMemorySize,
                         GEMM_SMEM_BYTES);
    cudaFuncSetAttribute(gemm_out, cudaFuncAttributeMaxDynamicSharedMemorySize,
                         GEMM_SMEM_BYTES);
    cudaFuncSetAttribute(flash_attn, cudaFuncAttributeMaxDynamicSharedMemorySize,
                         FLASH_SMEM_BYTES);

    // 1: fused tf32 pre-round (x + 4 weights)
    dim3 cgrid((W4 + 255) / 256, 1, 5);
    cvt_all<<<cgrid, 256>>>((const float4*)x, (const float4*)wq, (const float4*)wk,
                            (const float4*)wv, (const float4*)wo,
                            (float4*)xt, (float4*)wt);

    // 2: QKV projections, FUSED z=3 (1536 CTAs, amortized wave tails)
    dim3 qkv_grid(GM / 128, GN / 128, 3);
    gemm_qkv<<<qkv_grid, 256, GEMM_SMEM_BYTES>>>(xt);

    // 3: RoPE
    int npairs = SEQ * NHEAD * (HDIM / 2);
    rope_kernel<<<(npairs + 255) / 256, 256>>>(fc, fs);

    // 4: flash attention  (4th launch -> ncu profiles flash v5)
    flash_attn<<<dim3(SEQ / 64, NHEAD), 256, FLASH_SMEM_BYTES>>>();

    // 5: output projection
    dim3 ogrid(GM / 128, GN / 128);
    gemm_out<<<ogrid, 256, GEMM_SMEM_BYTES>>>(o, out);
}

// round 12
// speedup vs baseline: 2.7771x; 2.6166x over previous
#include <cuda_runtime.h>
#include <cuda_fp16.h>
#include <cstdint>
#include <mma.h>

using namespace nvcuda;

#define SEQ   2048
#define DIMSZ 4096
#define NHEAD 32
#define HDIM  128

// Scratch (device globals: allocation-free per harness rules)
__device__ float  g_q[(size_t)SEQ * DIMSZ];
__device__ float  g_k[(size_t)SEQ * DIMSZ];
__device__ float  g_v[(size_t)SEQ * DIMSZ];
__device__ float  g_o[(size_t)SEQ * DIMSZ];
__device__ __half g_xh[(size_t)SEQ * DIMSZ];             // fp16 x
__device__ __half g_wh[(size_t)4 * DIMSZ * DIMSZ];       // fp16 wq,wk,wv,wo
__device__ __half g_oh[(size_t)SEQ * DIMSZ];             // fp16 attention output

__device__ __forceinline__ float to_tf32(float x) { return wmma::__float_to_tf32(x); }

__device__ __forceinline__ void cp16(void* s, const void* g) {
    unsigned int sa = (unsigned int)__cvta_generic_to_shared(s);
    asm volatile("cp.async.cg.shared.global [%0], [%1], 16;" :: "r"(sa), "l"(g));
}
#define CP_COMMIT() asm volatile("cp.async.commit_group;")
#define CP_WAITG(n) asm volatile("cp.async.wait_group %0;" :: "n"(n))

// ---------------------------------------------------------------------------
// Fused fp16 conversion of x (z=0) and the 4 weights (z=1..4).
// Each thread: read float4, write 4 halves (8B).
// ---------------------------------------------------------------------------
#define W4 (DIMSZ * DIMSZ / 4)
#define X4 (SEQ * DIMSZ / 4)
__global__ void cvt_all(const float4* __restrict__ x,
                        const float4* __restrict__ w0, const float4* __restrict__ w1,
                        const float4* __restrict__ w2, const float4* __restrict__ w3)
{
    int z = blockIdx.z;
    int i = blockIdx.x * blockDim.x + threadIdx.x;
    const float4* src;
    __half2* dst;
    int n;
    if (z == 0)      { src = x;  dst = (__half2*)g_xh;                              n = X4; }
    else if (z == 1) { src = w0; dst = (__half2*)(g_wh);                            n = W4; }
    else if (z == 2) { src = w1; dst = (__half2*)(g_wh + (size_t)1 * DIMSZ * DIMSZ); n = W4; }
    else if (z == 3) { src = w2; dst = (__half2*)(g_wh + (size_t)2 * DIMSZ * DIMSZ); n = W4; }
    else             { src = w3; dst = (__half2*)(g_wh + (size_t)3 * DIMSZ * DIMSZ); n = W4; }
    if (i >= n) return;
    float4 v = src[i];
    dst[2 * i]     = __floats2half2_rn(v.x, v.y);
    dst[2 * i + 1] = __floats2half2_rn(v.z, v.w);
}

// ---------------------------------------------------------------------------
// GEMM: C[2048,4096] = A[2048,4096] @ B[4096,4096], fp16 in / fp32 accum.
// Block tile 128x128, BK=64 (halves), cp.async 3-stage pipeline.
// 256 thr = 8 warps, warp grid 4x2 (32x64 each), wmma m16n16k16.
// fp16 mantissa (10b) == tf32 mantissa -> same precision, 2x HMMA K-rate.
// ---------------------------------------------------------------------------
#define GM 2048
#define GN 4096
#define GK 4096
#define BKH 64
#define NTH (GK / BKH)   // 64
#define STAGES 3
#define LDAH 72          // halves per A row (64+8): 144B, 16B-multiple
#define LDBH 136         // halves per B row (128+8): 272B, 16B-multiple
#define ASTAGEH (128 * LDAH)
#define BSTAGEH (BKH * LDBH)
#define GEMM_SMEM_BYTES (STAGES * (ASTAGEH + BSTAGEH) * 2)

__device__ __forceinline__ void issue_stage(const __half* __restrict__ A,
                                            const __half* __restrict__ B,
                                            __half* As, __half* Bs,
                                            int bm, int bn, int kk, int tid)
{
    // A tile 128x64 halves: 8 chunks/row, 1024 chunks, 4/thread
#pragma unroll
    for (int i = 0; i < 4; i++) {
        int c = tid + i * 256;
        int r = c >> 3, k8 = (c & 7) << 3;
        cp16(&As[r * LDAH + k8], A + (size_t)(bm + r) * GK + kk + k8);
    }
    // B tile 64x128 halves: 16 chunks/row, 1024 chunks, 4/thread
#pragma unroll
    for (int i = 0; i < 4; i++) {
        int c = tid + i * 256;
        int r = c >> 4, c8 = (c & 15) << 3;
        cp16(&Bs[r * LDBH + c8], B + (size_t)(kk + r) * GN + bn + c8);
    }
}

__device__ __forceinline__ void gemm_core(const __half* __restrict__ A,
                                          const __half* __restrict__ B,
                                          float* __restrict__ C,
                                          __half* Ch,          // optional fp16 copy
                                          __half* sm, bool round_out)
{
    __half* As = sm;
    __half* Bs = sm + STAGES * ASTAGEH;

    const int tid = threadIdx.x;
    const int w   = tid >> 5;
    const int bm  = blockIdx.x * 128;
    const int bn  = blockIdx.y * 128;
    const int wr  = (w >> 1) * 32;
    const int wc  = (w & 1) * 64;

    wmma::fragment<wmma::accumulator, 16, 16, 16, float> acc[2][4];
#pragma unroll
    for (int i = 0; i < 2; i++)
#pragma unroll
        for (int j = 0; j < 4; j++) wmma::fill_fragment(acc[i][j], 0.0f);

    issue_stage(A, B, As, Bs, bm, bn, 0, tid);
    CP_COMMIT();
    issue_stage(A, B, As + ASTAGEH, Bs + BSTAGEH, bm, bn, BKH, tid);
    CP_COMMIT();

    for (int t = 0; t < NTH; t++) {
        CP_WAITG(1);
        __syncthreads();

        int nk = t + 2;
        if (nk < NTH) {
            int buf = nk % STAGES;
            issue_stage(A, B, As + buf * ASTAGEH, Bs + buf * BSTAGEH, bm, bn, nk * BKH, tid);
        }
        CP_COMMIT();

        const __half* Ac = As + (t % STAGES) * ASTAGEH;
        const __half* Bc = Bs + (t % STAGES) * BSTAGEH;
#pragma unroll
        for (int ks = 0; ks < 4; ks++) {     // 4 x k16 = BK 64
            wmma::fragment<wmma::matrix_a, 16, 16, 16, __half, wmma::row_major> a[2];
            wmma::fragment<wmma::matrix_b, 16, 16, 16, __half, wmma::row_major> b[4];
#pragma unroll
            for (int i = 0; i < 2; i++)
                wmma::load_matrix_sync(a[i], &Ac[(wr + i * 16) * LDAH + ks * 16], LDAH);
#pragma unroll
            for (int j = 0; j < 4; j++)
                wmma::load_matrix_sync(b[j], &Bc[(ks * 16) * LDBH + wc + j * 16], LDBH);
#pragma unroll
            for (int i = 0; i < 2; i++)
#pragma unroll
                for (int j = 0; j < 4; j++)
                    wmma::mma_sync(acc[i][j], a[i], b[j], acc[i][j]);
        }
    }

    if (round_out) {
#pragma unroll
        for (int i = 0; i < 2; i++)
#pragma unroll
            for (int j = 0; j < 4; j++)
#pragma unroll
                for (int t = 0; t < acc[i][j].num_elements; t++)
                    acc[i][j].x[t] = to_tf32(acc[i][j].x[t]);
    }

#pragma unroll
    for (int i = 0; i < 2; i++)
#pragma unroll
        for (int j = 0; j < 4; j++)
            wmma::store_matrix_sync(C + (size_t)(bm + wr + i * 16) * GN + bn + wc + j * 16,
                                    acc[i][j], GN, wmma::mem_row_major);
    (void)Ch;
}

__global__ __launch_bounds__(256, 2) void gemm_qkv()
{
    extern __shared__ __half smh[];
    const __half* B = g_wh + (size_t)blockIdx.z * DIMSZ * DIMSZ;
    float* C = (blockIdx.z == 0) ? g_q : (blockIdx.z == 1) ? g_k : g_v;
    gemm_core(g_xh, B, C, nullptr, smh, true);  // tf32-round Q/K/V for flash
}

__global__ __launch_bounds__(256, 2) void gemm_out(float* __restrict__ C)
{
    extern __shared__ __half smh[];
    gemm_core(g_oh, g_wh + (size_t)3 * DIMSZ * DIMSZ, C, nullptr, smh, false);
}

// ---------------------------------------------------------------------------
// RoPE applied in-place to g_q and g_k; outputs tf32-rounded.
// ---------------------------------------------------------------------------
__global__ void rope_kernel(const float* __restrict__ fcos, const float* __restrict__ fsin)
{
    int idx = blockIdx.x * blockDim.x + threadIdx.x;
    if (idx >= SEQ * NHEAD * (HDIM / 2)) return;
    int i = idx & 63;
    int h = (idx >> 6) & (NHEAD - 1);
    int s = idx >> 11;
    float c  = fcos[s * 64 + i];
    float sn = fsin[s * 64 + i];
    size_t off = (size_t)s * DIMSZ + h * HDIM + 2 * i;
    float q0 = g_q[off], q1 = g_q[off + 1];
    g_q[off]     = to_tf32(q0 * c - q1 * sn);
    g_q[off + 1] = to_tf32(q0 * sn + q1 * c);
    float k0 = g_k[off], k1 = g_k[off + 1];
    g_k[off]     = to_tf32(k0 * c - k1 * sn);
    g_k[off + 1] = to_tf32(k0 * sn + k1 * c);
}

// ---------------------------------------------------------------------------
// Flash attention v5 (unchanged from R11): register O accumulator,
// double-buffered K/V, register softmax state. Writes fp16 g_oh for the
// fp16 output GEMM (plus nothing else changes).
// ---------------------------------------------------------------------------
#define BKT 32
#define LDQ 132
#define LDS_S 36
#define FLASH_SMEM_FLOATS (64 * LDQ + 4 * BKT * LDQ + 64 * LDS_S + 3 * 64)
#define FLASH_SMEM_BYTES (FLASH_SMEM_FLOATS * 4)

__global__ __launch_bounds__(256, 2) void flash_attn()
{
    extern __shared__ float smf[];
    float* Qs   = smf;                      // 64 x LDQ
    float* Ks   = Qs + 64 * LDQ;            // 2 x 32 x LDQ
    float* Vs   = Ks + 2 * BKT * LDQ;       // 2 x 32 x LDQ
    float* Ss   = Vs + 2 * BKT * LDQ;       // 64 x LDS_S
    float* lrow = Ss + 64 * LDS_S;
    float* arow = lrow + 64;

    const int qb   = (gridDim.x - 1) - blockIdx.x;
    const int h    = blockIdx.y;
    const int tid  = threadIdx.x;
    const int w    = tid >> 5;
    const int lane = tid & 31;
    const float scale = 0.08838834764831845f;  // 1/sqrt(128)

    const float* Qg = g_q + (size_t)qb * 64 * DIMSZ + h * HDIM;
    const float* Kh = g_k + (size_t)h * HDIM;
    const float* Vh = g_v + (size_t)h * HDIM;

    const int owr = (w >> 2) * 32;
    const int owc = (w & 3) * 32;
    wmma::fragment<wmma::accumulator, 16, 16, 8, float> oacc[2][2];
#pragma unroll
    for (int i = 0; i < 2; i++)
#pragma unroll
        for (int j = 0; j < 2; j++) wmma::fill_fragment(oacc[i][j], 0.0f);

    const int srow = tid >> 2;
    const int ssub = tid & 3;
    float m_state = -1e30f;
    float l_state = 0.0f;

#pragma unroll
    for (int i = 0; i < 8; i++) {
        int idx = tid + i * 256;
        int r = idx >> 5, d4 = (idx & 31) << 2;
        cp16(&Qs[r * LDQ + d4], Qg + (size_t)r * DIMSZ + d4);
    }
#pragma unroll
    for (int i = 0; i < 4; i++) {
        int idx = tid + i * 256;
        int r = idx >> 5, d4 = (idx & 31) << 2;
        cp16(&Ks[r * LDQ + d4], Kh + (size_t)r * DIMSZ + d4);
        cp16(&Vs[r * LDQ + d4], Vh + (size_t)r * DIMSZ + d4);
    }
    CP_COMMIT();

    const int ntiles = 2 * qb + 2;

    for (int kt = 0; kt < ntiles; kt++) {
        const int buf = kt & 1;

        if (kt + 1 < ntiles) {
            float* Kn = Ks + (buf ^ 1) * BKT * LDQ;
            float* Vn = Vs + (buf ^ 1) * BKT * LDQ;
            const float* Kg = Kh + (size_t)(kt + 1) * BKT * DIMSZ;
            const float* Vg = Vh + (size_t)(kt + 1) * BKT * DIMSZ;
#pragma unroll
            for (int i = 0; i < 4; i++) {
                int idx = tid + i * 256;
                int r = idx >> 5, d4 = (idx & 31) << 2;
                cp16(&Kn[r * LDQ + d4], Kg + (size_t)r * DIMSZ + d4);
                cp16(&Vn[r * LDQ + d4], Vg + (size_t)r * DIMSZ + d4);
            }
            CP_COMMIT();
            CP_WAITG(1);
        } else {
            CP_WAITG(0);
        }
        __syncthreads();

        const float* Kc = Ks + buf * BKT * LDQ;
        const float* Vc = Vs + buf * BKT * LDQ;

        // S = scale * Q @ K^T : warp grid 4x2, each warp 16x16
        {
            const int wr = (w >> 1) * 16;
            const int wc = (w & 1) * 16;
            wmma::fragment<wmma::accumulator, 16, 16, 8, float> c;
            wmma::fill_fragment(c, 0.0f);
#pragma unroll
            for (int ks = 0; ks < 16; ks++) {
                wmma::fragment<wmma::matrix_a, 16, 16, 8, wmma::precision::tf32, wmma::row_major> a;
                wmma::fragment<wmma::matrix_b, 16, 16, 8, wmma::precision::tf32, wmma::col_major> b;
                wmma::load_matrix_sync(a, &Qs[wr * LDQ + ks * 8], LDQ);
                wmma::load_matrix_sync(b, &Kc[wc * LDQ + ks * 8], LDQ);
                wmma::mma_sync(c, a, b, c);
            }
#pragma unroll
            for (int t = 0; t < c.num_elements; t++) c.x[t] *= scale;
            wmma::store_matrix_sync(&Ss[wr * LDS_S + wc], c, LDS_S, wmma::mem_row_major);
        }
        __syncthreads();

        // Online softmax: state in registers; alpha -> smem for PV warps.
        {
            int lim = qb * 64 + srow - kt * BKT;
            int smax = lim + 1;
            if (smax > BKT) smax = BKT;
            if (smax < 0)   smax = 0;
            float mloc = -1e30f;
            int c0 = ssub * 8;
#pragma unroll
            for (int c = 0; c < 8; c++) {
                int cc = c0 + c;
                if (cc < smax) mloc = fmaxf(mloc, Ss[srow * LDS_S + cc]);
            }
#pragma unroll
            for (int o = 1; o < 4; o <<= 1)
                mloc = fmaxf(mloc, __shfl_xor_sync(0xffffffffu, mloc, o));
            float mn = fmaxf(m_state, mloc);
            float alpha = __expf(m_state - mn);
            float lsum = 0.0f;
#pragma unroll
            for (int c = 0; c < 8; c++) {
                int cc = c0 + c;
                float p = (cc < smax) ? __expf(Ss[srow * LDS_S + cc] - mn) : 0.0f;
                p = to_tf32(p);
                Ss[srow * LDS_S + cc] = p;
                lsum += p;
            }
#pragma unroll
            for (int o = 1; o < 4; o <<= 1)
                lsum += __shfl_xor_sync(0xffffffffu, lsum, o);
            l_state = l_state * alpha + lsum;
            m_state = mn;
            if (ssub == 0) arow[srow] = alpha;
        }
        __syncthreads();

        // Rescale O accumulator in registers
        {
            const int r0 = lane >> 2;
#pragma unroll
            for (int i = 0; i < 2; i++) {
                float a0 = arow[owr + i * 16 + r0];
                float a1 = arow[owr + i * 16 + r0 + 8];
#pragma unroll
                for (int j = 0; j < 2; j++)
#pragma unroll
                    for (int e = 0; e < 8; e++)
                        oacc[i][j].x[e] *= ((e & 3) >= 2) ? a1 : a0;
            }
        }

        // O += P @ V
        {
#pragma unroll
            for (int ks = 0; ks < 4; ks++) {
                wmma::fragment<wmma::matrix_a, 16, 16, 8, wmma::precision::tf32, wmma::row_major> a[2];
                wmma::fragment<wmma::matrix_b, 16, 16, 8, wmma::precision::tf32, wmma::row_major> b[2];
#pragma unroll
                for (int i = 0; i < 2; i++)
                    wmma::load_matrix_sync(a[i], &Ss[(owr + i * 16) * LDS_S + ks * 8], LDS_S);
#pragma unroll
                for (int j = 0; j < 2; j++)
                    wmma::load_matrix_sync(b[j], &Vc[(ks * 8) * LDQ + owc + j * 16], LDQ);
#pragma unroll
                for (int i = 0; i < 2; i++)
#pragma unroll
                    for (int j = 0; j < 2; j++)
                        wmma::mma_sync(oacc[i][j], a[i], b[j], oacc[i][j]);
            }
        }
        __syncthreads();
    }

    if (ssub == 0) lrow[srow] = l_state;
    __syncthreads();

    // Epilogue: normalize in registers, store fp16 to g_oh for the fp16
    // output GEMM. Reuse Ss region as a 32x33 staging buffer per warp? No —
    // store via smem-free path: write fp32 fragment values to g_oh with
    // element mapping (row = lane/4 + 8*(e%4>=2), col = (lane%4)*2 + e%2 + 8*(e>=4)).
    __half* Og = g_oh + (size_t)qb * 64 * DIMSZ + h * HDIM;
    {
        const int r0 = lane >> 2;
        const int c0 = (lane & 3) * 2;
#pragma unroll
        for (int i = 0; i < 2; i++) {
            float inv0 = 1.0f / lrow[owr + i * 16 + r0];
            float inv1 = 1.0f / lrow[owr + i * 16 + r0 + 8];
#pragma unroll
            for (int j = 0; j < 2; j++) {
#pragma unroll
                for (int e = 0; e < 8; e++) {
                    float v = oacc[i][j].x[e] * (((e & 3) >= 2) ? inv1 : inv0);
                    int row = owr + i * 16 + r0 + (((e & 3) >= 2) ? 8 : 0);
                    int col = owc + j * 16 + c0 + (e & 1) + ((e >= 4) ? 8 : 0);
                    Og[(size_t)row * DIMSZ + col] = __float2half_rn(v);
                }
            }
        }
    }
}

// ---------------------------------------------------------------------------
extern "C" void kernel_launch(void* const* d_in, const int* in_sizes, int n_in,
                              void* d_out, int out_size)
{
    const float* x  = (const float*)d_in[0];
    const float* wq = (const float*)d_in[1];
    const float* wk = (const float*)d_in[2];
    const float* wv = (const float*)d_in[3];
    const float* wo = (const float*)d_in[4];
    const float* fc = (const float*)d_in[5];
    const float* fs = (const float*)d_in[6];
    float* out = (float*)d_out;

    cudaFuncSetAttribute(gemm_qkv, cudaFuncAttributeMaxDynamicSharedMemorySize,
                         GEMM_SMEM_BYTES);
    cudaFuncSetAttribute(gemm_out, cudaFuncAttributeMaxDynamicSharedMemorySize,
                         GEMM_SMEM_BYTES);
    cudaFuncSetAttribute(flash_attn, cudaFuncAttributeMaxDynamicSharedMemorySize,
                         FLASH_SMEM_BYTES);

    // 1: fused fp16 conversion (x + 4 weights)
    dim3 cgrid((W4 + 255) / 256, 1, 5);
    cvt_all<<<cgrid, 256>>>((const float4*)x, (const float4*)wq, (const float4*)wk,
                            (const float4*)wv, (const float4*)wo);

    // 2: QKV projections, fused z=3, fp16 HMMA
    dim3 qkv_grid(GM / 128, GN / 128, 3);
    gemm_qkv<<<qkv_grid, 256, GEMM_SMEM_BYTES>>>();

    // 3: RoPE
    int npairs = SEQ * NHEAD * (HDIM / 2);
    rope_kernel<<<(npairs + 255) / 256, 256>>>(fc, fs);

    // 4: flash attention (control; profiled)
    flash_attn<<<dim3(SEQ / 64, NHEAD), 256, FLASH_SMEM_BYTES>>>();

    // 5: output projection, fp16 HMMA
    dim3 ogrid(GM / 128, GN / 128);
    gemm_out<<<ogrid, 256, GEMM_SMEM_BYTES>>>(out);
}

// round 13
// speedup vs baseline: 4.0930x; 1.4739x over previous
#include <cuda_runtime.h>
#include <cuda_fp16.h>
#include <cstdint>
#include <mma.h>

using namespace nvcuda;

#define SEQ   2048
#define DIMSZ 4096
#define NHEAD 32
#define HDIM  128

// Scratch (device globals: allocation-free per harness rules)
__device__ float  g_q[(size_t)SEQ * DIMSZ];              // fp32 Q (pre-rope)
__device__ float  g_k[(size_t)SEQ * DIMSZ];              // fp32 K (pre-rope)
__device__ float  g_v[(size_t)SEQ * DIMSZ];              // fp32 V
__device__ __half g_qh[(size_t)SEQ * DIMSZ];             // fp16 Q (post-rope)
__device__ __half g_kh[(size_t)SEQ * DIMSZ];             // fp16 K (post-rope)
__device__ __half g_vh[(size_t)SEQ * DIMSZ];             // fp16 V
__device__ __half g_xh[(size_t)SEQ * DIMSZ];             // fp16 x
__device__ __half g_wh[(size_t)4 * DIMSZ * DIMSZ];       // fp16 wq,wk,wv,wo
__device__ __half g_oh[(size_t)SEQ * DIMSZ];             // fp16 attention output

__device__ __forceinline__ void cp16(void* s, const void* g) {
    unsigned int sa = (unsigned int)__cvta_generic_to_shared(s);
    asm volatile("cp.async.cg.shared.global [%0], [%1], 16;" :: "r"(sa), "l"(g));
}
#define CP_COMMIT() asm volatile("cp.async.commit_group;")
#define CP_WAITG(n) asm volatile("cp.async.wait_group %0;" :: "n"(n))

// ---------------------------------------------------------------------------
// Fused fp16 conversion of x (z=0) and the 4 weights (z=1..4).
// ---------------------------------------------------------------------------
#define W4 (DIMSZ * DIMSZ / 4)
#define X4 (SEQ * DIMSZ / 4)
__global__ void cvt_all(const float4* __restrict__ x,
                        const float4* __restrict__ w0, const float4* __restrict__ w1,
                        const float4* __restrict__ w2, const float4* __restrict__ w3)
{
    int z = blockIdx.z;
    int i = blockIdx.x * blockDim.x + threadIdx.x;
    const float4* src;
    __half2* dst;
    int n;
    if (z == 0)      { src = x;  dst = (__half2*)g_xh;                               n = X4; }
    else if (z == 1) { src = w0; dst = (__half2*)(g_wh);                             n = W4; }
    else if (z == 2) { src = w1; dst = (__half2*)(g_wh + (size_t)1 * DIMSZ * DIMSZ); n = W4; }
    else if (z == 3) { src = w2; dst = (__half2*)(g_wh + (size_t)2 * DIMSZ * DIMSZ); n = W4; }
    else             { src = w3; dst = (__half2*)(g_wh + (size_t)3 * DIMSZ * DIMSZ); n = W4; }
    if (i >= n) return;
    float4 v = src[i];
    dst[2 * i]     = __floats2half2_rn(v.x, v.y);
    dst[2 * i + 1] = __floats2half2_rn(v.z, v.w);
}

// ---------------------------------------------------------------------------
// GEMM: C = A @ B, fp16 in / fp32 accum. Block 128x128, BK=64, 3-stage
// cp.async. 256 thr, warp grid 4x2 (32x64), wmma m16n16k16. (R12-proven.)
// ---------------------------------------------------------------------------
#define GM 2048
#define GN 4096
#define GK 4096
#define BKH 64
#define NTH (GK / BKH)   // 64
#define STAGES 3
#define LDAH 72
#define LDBH 136
#define ASTAGEH (128 * LDAH)
#define BSTAGEH (BKH * LDBH)
#define GEMM_SMEM_BYTES (STAGES * (ASTAGEH + BSTAGEH) * 2)

__device__ __forceinline__ void issue_stage(const __half* __restrict__ A,
                                            const __half* __restrict__ B,
                                            __half* As, __half* Bs,
                                            int bm, int bn, int kk, int tid)
{
#pragma unroll
    for (int i = 0; i < 4; i++) {
        int c = tid + i * 256;
        int r = c >> 3, k8 = (c & 7) << 3;
        cp16(&As[r * LDAH + k8], A + (size_t)(bm + r) * GK + kk + k8);
    }
#pragma unroll
    for (int i = 0; i < 4; i++) {
        int c = tid + i * 256;
        int r = c >> 4, c8 = (c & 15) << 3;
        cp16(&Bs[r * LDBH + c8], B + (size_t)(kk + r) * GN + bn + c8);
    }
}

__device__ __forceinline__ void gemm_core(const __half* __restrict__ A,
                                          const __half* __restrict__ B,
                                          float* __restrict__ C,
                                          __half* sm)
{
    __half* As = sm;
    __half* Bs = sm + STAGES * ASTAGEH;

    const int tid = threadIdx.x;
    const int w   = tid >> 5;
    const int bm  = blockIdx.x * 128;
    const int bn  = blockIdx.y * 128;
    const int wr  = (w >> 1) * 32;
    const int wc  = (w & 1) * 64;

    wmma::fragment<wmma::accumulator, 16, 16, 16, float> acc[2][4];
#pragma unroll
    for (int i = 0; i < 2; i++)
#pragma unroll
        for (int j = 0; j < 4; j++) wmma::fill_fragment(acc[i][j], 0.0f);

    issue_stage(A, B, As, Bs, bm, bn, 0, tid);
    CP_COMMIT();
    issue_stage(A, B, As + ASTAGEH, Bs + BSTAGEH, bm, bn, BKH, tid);
    CP_COMMIT();

    for (int t = 0; t < NTH; t++) {
        CP_WAITG(1);
        __syncthreads();

        int nk = t + 2;
        if (nk < NTH) {
            int buf = nk % STAGES;
            issue_stage(A, B, As + buf * ASTAGEH, Bs + buf * BSTAGEH, bm, bn, nk * BKH, tid);
        }
        CP_COMMIT();

        const __half* Ac = As + (t % STAGES) * ASTAGEH;
        const __half* Bc = Bs + (t % STAGES) * BSTAGEH;
#pragma unroll
        for (int ks = 0; ks < 4; ks++) {
            wmma::fragment<wmma::matrix_a, 16, 16, 16, __half, wmma::row_major> a[2];
            wmma::fragment<wmma::matrix_b, 16, 16, 16, __half, wmma::row_major> b[4];
#pragma unroll
            for (int i = 0; i < 2; i++)
                wmma::load_matrix_sync(a[i], &Ac[(wr + i * 16) * LDAH + ks * 16], LDAH);
#pragma unroll
            for (int j = 0; j < 4; j++)
                wmma::load_matrix_sync(b[j], &Bc[(ks * 16) * LDBH + wc + j * 16], LDBH);
#pragma unroll
            for (int i = 0; i < 2; i++)
#pragma unroll
                for (int j = 0; j < 4; j++)
                    wmma::mma_sync(acc[i][j], a[i], b[j], acc[i][j]);
        }
    }

#pragma unroll
    for (int i = 0; i < 2; i++)
#pragma unroll
        for (int j = 0; j < 4; j++)
            wmma::store_matrix_sync(C + (size_t)(bm + wr + i * 16) * GN + bn + wc + j * 16,
                                    acc[i][j], GN, wmma::mem_row_major);
}

__global__ __launch_bounds__(256, 2) void gemm_qkv()
{
    extern __shared__ __half smh[];
    const __half* B = g_wh + (size_t)blockIdx.z * DIMSZ * DIMSZ;
    float* C = (blockIdx.z == 0) ? g_q : (blockIdx.z == 1) ? g_k : g_v;
    gemm_core(g_xh, B, C, smh);
}

__global__ __launch_bounds__(256, 2) void gemm_out(float* __restrict__ C)
{
    extern __shared__ __half smh[];
    gemm_core(g_oh, g_wh + (size_t)3 * DIMSZ * DIMSZ, C, smh);
}

// ---------------------------------------------------------------------------
// RoPE: rotate fp32 Q/K -> fp16 g_qh/g_kh; convert V -> fp16 in same pass.
// ---------------------------------------------------------------------------
__global__ void rope_kernel(const float* __restrict__ fcos, const float* __restrict__ fsin)
{
    int idx = blockIdx.x * blockDim.x + threadIdx.x;
    if (idx >= SEQ * NHEAD * (HDIM / 2)) return;
    int i = idx & 63;
    int h = (idx >> 6) & (NHEAD - 1);
    int s = idx >> 11;
    float c  = fcos[s * 64 + i];
    float sn = fsin[s * 64 + i];
    size_t off = (size_t)s * DIMSZ + h * HDIM + 2 * i;
    float q0 = g_q[off], q1 = g_q[off + 1];
    *(__half2*)&g_qh[off] = __floats2half2_rn(q0 * c - q1 * sn, q0 * sn + q1 * c);
    float k0 = g_k[off], k1 = g_k[off + 1];
    *(__half2*)&g_kh[off] = __floats2half2_rn(k0 * c - k1 * sn, k0 * sn + k1 * c);
    *(__half2*)&g_vh[off] = __floats2half2_rn(g_v[off], g_v[off + 1]);
}

// ---------------------------------------------------------------------------
// Flash attention v6: full fp16 datapath. q-tile 64, k-tile 64 (BKT doubled
// -> iterations/barriers halved), m16n16k16 HMMA, fp32 accum. Register O
// accumulator + register softmax state + double-buffered K/V.
// SMEM = 114.2 KB -> 2 CTAs/SM.
// ---------------------------------------------------------------------------
#define BKT 64
#define LDQH2 136   // halves per row (128+8); 272B rows, 16B-multiple
#define LDS_S 68    // fp32 scores (64+4)
#define LDPH 72     // fp16 P (64+8)
// halves: Q 64*136, K 2*64*136, V 2*64*136; then fp32 Ss 64*68 + 128; then P
#define FLASH_HALVES (5 * 64 * LDQH2)
#define FLASH_SMEM_BYTES (FLASH_HALVES * 2 + (64 * LDS_S + 128) * 4 + 64 * LDPH * 2)

__global__ __launch_bounds__(256, 2) void flash_attn()
{
    extern __shared__ __half smh[];
    __half* Qs = smh;                        // 64 x LDQH2
    __half* Ks = Qs + 64 * LDQH2;            // 2 x 64 x LDQH2
    __half* Vs = Ks + 2 * 64 * LDQH2;        // 2 x 64 x LDQH2
    float*  Ss = (float*)(Vs + 2 * 64 * LDQH2);   // 64 x LDS_S fp32
    float*  lrow = Ss + 64 * LDS_S;          // 64
    float*  arow = lrow + 64;                // 64
    __half* Ps = (__half*)(arow + 64);       // 64 x LDPH fp16

    const int qb   = (gridDim.x - 1) - blockIdx.x;   // long blocks first
    const int h    = blockIdx.y;
    const int tid  = threadIdx.x;
    const int w    = tid >> 5;
    const int lane = tid & 31;
    const float scale = 0.08838834764831845f;  // 1/sqrt(128)

    const __half* Qg = g_qh + (size_t)qb * 64 * DIMSZ + h * HDIM;
    const __half* Kh = g_kh + (size_t)h * HDIM;
    const __half* Vh = g_vh + (size_t)h * HDIM;

    // O ownership (PV warp grid 2x4)
    const int owr = (w >> 2) * 32;
    const int owc = (w & 3) * 32;
    wmma::fragment<wmma::accumulator, 16, 16, 16, float> oacc[2][2];
#pragma unroll
    for (int i = 0; i < 2; i++)
#pragma unroll
        for (int j = 0; j < 2; j++) wmma::fill_fragment(oacc[i][j], 0.0f);

    // Register softmax state: thread group (r = tid>>2) owns row r.
    const int srow = tid >> 2;
    const int ssub = tid & 3;
    float m_state = -1e30f;
    float l_state = 0.0f;

    // Prologue: Q + K0/V0. 64x128 halves = 1024 16B-chunks each, 4/thread.
#pragma unroll
    for (int i = 0; i < 4; i++) {
        int idx = tid + i * 256;
        int r = idx >> 4, c8 = (idx & 15) << 3;
        cp16(&Qs[r * LDQH2 + c8], Qg + (size_t)r * DIMSZ + c8);
        cp16(&Ks[r * LDQH2 + c8], Kh + (size_t)r * DIMSZ + c8);
        cp16(&Vs[r * LDQH2 + c8], Vh + (size_t)r * DIMSZ + c8);
    }
    CP_COMMIT();

    const int ntiles = qb + 1;   // 64-row k-tiles up to and incl. diagonal

    for (int kt = 0; kt < ntiles; kt++) {
        const int buf = kt & 1;

        if (kt + 1 < ntiles) {
            __half* Kn = Ks + (buf ^ 1) * 64 * LDQH2;
            __half* Vn = Vs + (buf ^ 1) * 64 * LDQH2;
            const __half* Kg = Kh + (size_t)(kt + 1) * 64 * DIMSZ;
            const __half* Vg = Vh + (size_t)(kt + 1) * 64 * DIMSZ;
#pragma unroll
            for (int i = 0; i < 4; i++) {
                int idx = tid + i * 256;
                int r = idx >> 4, c8 = (idx & 15) << 3;
                cp16(&Kn[r * LDQH2 + c8], Kg + (size_t)r * DIMSZ + c8);
                cp16(&Vn[r * LDQH2 + c8], Vg + (size_t)r * DIMSZ + c8);
            }
            CP_COMMIT();
            CP_WAITG(1);
        } else {
            CP_WAITG(0);
        }
        __syncthreads();    // current K/V (+Q first iter) visible

        const __half* Kc = Ks + buf * 64 * LDQH2;
        const __half* Vc = Vs + buf * 64 * LDQH2;

        // S = scale * Q @ K^T : warp grid 4x2, each warp 16 rows x 32 cols
        {
            const int wr = (w >> 1) * 16;
            const int wc = (w & 1) * 32;
            wmma::fragment<wmma::accumulator, 16, 16, 16, float> c[2];
            wmma::fill_fragment(c[0], 0.0f);
            wmma::fill_fragment(c[1], 0.0f);
#pragma unroll
            for (int ks = 0; ks < 8; ks++) {
                wmma::fragment<wmma::matrix_a, 16, 16, 16, __half, wmma::row_major> a;
                wmma::load_matrix_sync(a, &Qs[wr * LDQH2 + ks * 16], LDQH2);
#pragma unroll
                for (int j = 0; j < 2; j++) {
                    wmma::fragment<wmma::matrix_b, 16, 16, 16, __half, wmma::col_major> b;
                    wmma::load_matrix_sync(b, &Kc[(wc + j * 16) * LDQH2 + ks * 16], LDQH2);
                    wmma::mma_sync(c[j], a, b, c[j]);
                }
            }
#pragma unroll
            for (int j = 0; j < 2; j++) {
#pragma unroll
                for (int t = 0; t < c[j].num_elements; t++) c[j].x[t] *= scale;
                wmma::store_matrix_sync(&Ss[wr * LDS_S + wc + j * 16], c[j], LDS_S,
                                        wmma::mem_row_major);
            }
        }
        __syncthreads();    // S visible

        // Online softmax: 4 threads/row, 16 cols each; P -> fp16 Ps.
        {
            int lim = qb * 64 + srow - kt * 64;
            int smax = lim + 1;
            if (smax > BKT) smax = BKT;
            if (smax < 0)   smax = 0;
            float mloc = -1e30f;
            int c0 = ssub * 16;
#pragma unroll
            for (int c = 0; c < 16; c++) {
                int cc = c0 + c;
                if (cc < smax) mloc = fmaxf(mloc, Ss[srow * LDS_S + cc]);
            }
#pragma unroll
            for (int o = 1; o < 4; o <<= 1)
                mloc = fmaxf(mloc, __shfl_xor_sync(0xffffffffu, mloc, o));
            float mn = fmaxf(m_state, mloc);
            float alpha = __expf(m_state - mn);
            float lsum = 0.0f;
#pragma unroll
            for (int c = 0; c < 16; c += 2) {
                int cc = c0 + c;
                float p0 = (cc < smax)     ? __expf(Ss[srow * LDS_S + cc] - mn)     : 0.0f;
                float p1 = (cc + 1 < smax) ? __expf(Ss[srow * LDS_S + cc + 1] - mn) : 0.0f;
                *(__half2*)&Ps[srow * LDPH + cc] = __floats2half2_rn(p0, p1);
                lsum += p0 + p1;
            }
#pragma unroll
            for (int o = 1; o < 4; o <<= 1)
                lsum += __shfl_xor_sync(0xffffffffu, lsum, o);
            l_state = l_state * alpha + lsum;
            m_state = mn;
            if (ssub == 0) arow[srow] = alpha;
        }
        __syncthreads();    // P + arow visible

        // Rescale O accumulator in registers (row map: lane/4, +8 for e%4>=2)
        {
            const int r0 = lane >> 2;
#pragma unroll
            for (int i = 0; i < 2; i++) {
                float a0 = arow[owr + i * 16 + r0];
                float a1 = arow[owr + i * 16 + r0 + 8];
#pragma unroll
                for (int j = 0; j < 2; j++)
#pragma unroll
                    for (int e = 0; e < 8; e++)
                        oacc[i][j].x[e] *= ((e & 3) >= 2) ? a1 : a0;
            }
        }

        // O += P @ V : warp grid 2x4, each warp 32x32, 4 k-steps of 16
        {
#pragma unroll
            for (int ks = 0; ks < 4; ks++) {
                wmma::fragment<wmma::matrix_a, 16, 16, 16, __half, wmma::row_major> a[2];
                wmma::fragment<wmma::matrix_b, 16, 16, 16, __half, wmma::row_major> b[2];
#pragma unroll
                for (int i = 0; i < 2; i++)
                    wmma::load_matrix_sync(a[i], &Ps[(owr + i * 16) * LDPH + ks * 16], LDPH);
#pragma unroll
                for (int j = 0; j < 2; j++)
                    wmma::load_matrix_sync(b[j], &Vc[(ks * 16) * LDQH2 + owc + j * 16], LDQH2);
#pragma unroll
                for (int i = 0; i < 2; i++)
#pragma unroll
                    for (int j = 0; j < 2; j++)
                        wmma::mma_sync(oacc[i][j], a[i], b[j], oacc[i][j]);
            }
        }
        __syncthreads();    // Ps/Vc/Kc readers done
    }

    // Publish l, then normalize in registers and store fp16 to g_oh.
    if (ssub == 0) lrow[srow] = l_state;
    __syncthreads();

    __half* Og = g_oh + (size_t)qb * 64 * DIMSZ + h * HDIM;
    {
        const int r0 = lane >> 2;
        const int c0 = (lane & 3) * 2;
#pragma unroll
        for (int i = 0; i < 2; i++) {
            float inv0 = 1.0f / lrow[owr + i * 16 + r0];
            float inv1 = 1.0f / lrow[owr + i * 16 + r0 + 8];
#pragma unroll
            for (int j = 0; j < 2; j++) {
#pragma unroll
                for (int e = 0; e < 8; e++) {
                    float v = oacc[i][j].x[e] * (((e & 3) >= 2) ? inv1 : inv0);
                    int row = owr + i * 16 + r0 + (((e & 3) >= 2) ? 8 : 0);
                    int col = owc + j * 16 + c0 + (e & 1) + ((e >= 4) ? 8 : 0);
                    Og[(size_t)row * DIMSZ + col] = __float2half_rn(v);
                }
            }
        }
    }
}

// ---------------------------------------------------------------------------
extern "C" void kernel_launch(void* const* d_in, const int* in_sizes, int n_in,
                              void* d_out, int out_size)
{
    const float* x  = (const float*)d_in[0];
    const float* wq = (const float*)d_in[1];
    const float* wk = (const float*)d_in[2];
    const float* wv = (const float*)d_in[3];
    const float* wo = (const float*)d_in[4];
    const float* fc = (const float*)d_in[5];
    const float* fs = (const float*)d_in[6];
    float* out = (float*)d_out;

    cudaFuncSetAttribute(gemm_qkv, cudaFuncAttributeMaxDynamicSharedMemorySize,
                         GEMM_SMEM_BYTES);
    cudaFuncSetAttribute(gemm_out, cudaFuncAttributeMaxDynamicSharedMemorySize,
                         GEMM_SMEM_BYTES);
    cudaFuncSetAttribute(flash_attn, cudaFuncAttributeMaxDynamicSharedMemorySize,
                         FLASH_SMEM_BYTES);

    // 1: fused fp16 conversion (x + 4 weights)
    dim3 cgrid((W4 + 255) / 256, 1, 5);
    cvt_all<<<cgrid, 256>>>((const float4*)x, (const float4*)wq, (const float4*)wk,
                            (const float4*)wv, (const float4*)wo);

    // 2: QKV projections, fused z=3, fp16 HMMA
    dim3 qkv_grid(GM / 128, GN / 128, 3);
    gemm_qkv<<<qkv_grid, 256, GEMM_SMEM_BYTES>>>();

    // 3: RoPE (-> fp16 Q/K) + V fp16 conversion
    int npairs = SEQ * NHEAD * (HDIM / 2);
    rope_kernel<<<(npairs + 255) / 256, 256>>>(fc, fs);

    // 4: flash attention v6 (fp16; profiled)
    flash_attn<<<dim3(SEQ / 64, NHEAD), 256, FLASH_SMEM_BYTES>>>();

    // 5: output projection, fp16 HMMA
    dim3 ogrid(GM / 128, GN / 128);
    gemm_out<<<ogrid, 256, GEMM_SMEM_BYTES>>>(out);
}

// round 14
// speedup vs baseline: 4.3856x; 1.0715x over previous
#include <cuda_runtime.h>
#include <cuda_fp16.h>
#include <cstdint>
#include <mma.h>

using namespace nvcuda;

#define SEQ   2048
#define DIMSZ 4096
#define NHEAD 32
#define HDIM  128

// Scratch (device globals: allocation-free per harness rules)
__device__ __half g_qh[(size_t)SEQ * DIMSZ];             // fp16 Q (post-rope)
__device__ __half g_kh[(size_t)SEQ * DIMSZ];             // fp16 K (post-rope)
__device__ __half g_vh[(size_t)SEQ * DIMSZ];             // fp16 V
__device__ __half g_xh[(size_t)SEQ * DIMSZ];             // fp16 x
__device__ __half g_wh[(size_t)4 * DIMSZ * DIMSZ];       // fp16 wq,wk,wv,wo
__device__ __half g_oh[(size_t)SEQ * DIMSZ];             // fp16 attention output

__device__ __forceinline__ void cp16(void* s, const void* g) {
    unsigned int sa = (unsigned int)__cvta_generic_to_shared(s);
    asm volatile("cp.async.cg.shared.global [%0], [%1], 16;" :: "r"(sa), "l"(g));
}
#define CP_COMMIT() asm volatile("cp.async.commit_group;")
#define CP_WAITG(n) asm volatile("cp.async.wait_group %0;" :: "n"(n))

// ---------------------------------------------------------------------------
// Fused fp16 conversion of x (z=0) and the 4 weights (z=1..4).
// ---------------------------------------------------------------------------
#define W4 (DIMSZ * DIMSZ / 4)
#define X4 (SEQ * DIMSZ / 4)
__global__ void cvt_all(const float4* __restrict__ x,
                        const float4* __restrict__ w0, const float4* __restrict__ w1,
                        const float4* __restrict__ w2, const float4* __restrict__ w3)
{
    int z = blockIdx.z;
    int i = blockIdx.x * blockDim.x + threadIdx.x;
    const float4* src;
    __half2* dst;
    int n;
    if (z == 0)      { src = x;  dst = (__half2*)g_xh;                               n = X4; }
    else if (z == 1) { src = w0; dst = (__half2*)(g_wh);                             n = W4; }
    else if (z == 2) { src = w1; dst = (__half2*)(g_wh + (size_t)1 * DIMSZ * DIMSZ); n = W4; }
    else if (z == 3) { src = w2; dst = (__half2*)(g_wh + (size_t)2 * DIMSZ * DIMSZ); n = W4; }
    else             { src = w3; dst = (__half2*)(g_wh + (size_t)3 * DIMSZ * DIMSZ); n = W4; }
    if (i >= n) return;
    float4 v = src[i];
    dst[2 * i]     = __floats2half2_rn(v.x, v.y);
    dst[2 * i + 1] = __floats2half2_rn(v.z, v.w);
}

// ---------------------------------------------------------------------------
// GEMM mainloop: acc += A[bm:+128] @ B[:, bn:+128], fp16 in / fp32 accum.
// Block 128x128, BK=64, 3-stage cp.async. 256 thr, warp grid 4x2 (32x64).
// ---------------------------------------------------------------------------
#define GM 2048
#define GN 4096
#define GK 4096
#define BKH 64
#define NTH (GK / BKH)   // 64
#define STAGES 3
#define LDAH 72
#define LDBH 136
#define ASTAGEH (128 * LDAH)
#define BSTAGEH (BKH * LDBH)
#define GEMM_SMEM_BYTES (STAGES * (ASTAGEH + BSTAGEH) * 2)   // 107.5 KB

__device__ __forceinline__ void issue_stage(const __half* __restrict__ A,
                                            const __half* __restrict__ B,
                                            __half* As, __half* Bs,
                                            int bm, int bn, int kk, int tid)
{
#pragma unroll
    for (int i = 0; i < 4; i++) {
        int c = tid + i * 256;
        int r = c >> 3, k8 = (c & 7) << 3;
        cp16(&As[r * LDAH + k8], A + (size_t)(bm + r) * GK + kk + k8);
    }
#pragma unroll
    for (int i = 0; i < 4; i++) {
        int c = tid + i * 256;
        int r = c >> 4, c8 = (c & 15) << 3;
        cp16(&Bs[r * LDBH + c8], B + (size_t)(kk + r) * GN + bn + c8);
    }
}

__device__ __forceinline__ void gemm_mainloop(
    const __half* __restrict__ A, const __half* __restrict__ B, __half* sm,
    wmma::fragment<wmma::accumulator, 16, 16, 16, float> (&acc)[2][4],
    int bm, int bn, int wr, int wc, int tid)
{
    __half* As = sm;
    __half* Bs = sm + STAGES * ASTAGEH;

#pragma unroll
    for (int i = 0; i < 2; i++)
#pragma unroll
        for (int j = 0; j < 4; j++) wmma::fill_fragment(acc[i][j], 0.0f);

    issue_stage(A, B, As, Bs, bm, bn, 0, tid);
    CP_COMMIT();
    issue_stage(A, B, As + ASTAGEH, Bs + BSTAGEH, bm, bn, BKH, tid);
    CP_COMMIT();

    for (int t = 0; t < NTH; t++) {
        CP_WAITG(1);
        __syncthreads();

        int nk = t + 2;
        if (nk < NTH) {
            int buf = nk % STAGES;
            issue_stage(A, B, As + buf * ASTAGEH, Bs + buf * BSTAGEH, bm, bn, nk * BKH, tid);
        }
        CP_COMMIT();

        const __half* Ac = As + (t % STAGES) * ASTAGEH;
        const __half* Bc = Bs + (t % STAGES) * BSTAGEH;
#pragma unroll
        for (int ks = 0; ks < 4; ks++) {
            wmma::fragment<wmma::matrix_a, 16, 16, 16, __half, wmma::row_major> a[2];
            wmma::fragment<wmma::matrix_b, 16, 16, 16, __half, wmma::row_major> b[4];
#pragma unroll
            for (int i = 0; i < 2; i++)
                wmma::load_matrix_sync(a[i], &Ac[(wr + i * 16) * LDAH + ks * 16], LDAH);
#pragma unroll
            for (int j = 0; j < 4; j++)
                wmma::load_matrix_sync(b[j], &Bc[(ks * 16) * LDBH + wc + j * 16], LDBH);
#pragma unroll
            for (int i = 0; i < 2; i++)
#pragma unroll
                for (int j = 0; j < 4; j++)
                    wmma::mma_sync(acc[i][j], a[i], b[j], acc[i][j]);
        }
    }
}

// ---------------------------------------------------------------------------
// QKV GEMM with FUSED rope (z=0,1) / fp16 convert (z=2) epilogue.
// N-tile (128 cols) == exactly one head, so cols 0..127 of the tile map to
// head-dims 0..127; rope pair index i = local_col/2. cos/sin tiles staged in
// the (now free) GEMM smem. Accumulator e-pair mapping verified in R12/13:
// row = r0 + 8*((e&3)>=2), col = c0 + (e&1) + 8*(e>=4); pairs (e, e+1), e even.
// ---------------------------------------------------------------------------
__global__ __launch_bounds__(256, 2) void gemm_qkv(const float* __restrict__ fc,
                                                   const float* __restrict__ fs)
{
    extern __shared__ __half smh[];
    const int z   = blockIdx.z;
    const int tid = threadIdx.x;
    const int w   = tid >> 5;
    const int lane = tid & 31;
    const int bm  = blockIdx.x * 128;
    const int bn  = blockIdx.y * 128;
    const int wr  = (w >> 1) * 32;
    const int wc  = (w & 1) * 64;

    wmma::fragment<wmma::accumulator, 16, 16, 16, float> acc[2][4];
    gemm_mainloop(g_xh, g_wh + (size_t)z * DIMSZ * DIMSZ, smh, acc, bm, bn, wr, wc, tid);

    __syncthreads();   // mainloop smem reads done; safe to overlay

    // Stage cos/sin tiles for rows bm..bm+127 (only needed for Q/K).
    float* fcs = (float*)smh;            // [128][64]
    float* fsn = fcs + 128 * 64;         // [128][64]  (total 64 KB)
    if (z < 2) {
        const float4* fc4 = (const float4*)fc;
        const float4* fs4 = (const float4*)fs;
        for (int i = tid; i < 2048; i += 256) {     // 128 rows x 16 float4
            ((float4*)fcs)[i] = fc4[bm * 16 + i];
            ((float4*)fsn)[i] = fs4[bm * 16 + i];
        }
    }
    __syncthreads();

    __half* dst = (z == 0) ? g_qh : (z == 1) ? g_kh : g_vh;
    const int r0 = lane >> 2;
    const int c0 = (lane & 3) * 2;
#pragma unroll
    for (int i16 = 0; i16 < 2; i16++) {
#pragma unroll
        for (int j = 0; j < 4; j++) {
#pragma unroll
            for (int e = 0; e < 8; e += 2) {
                int row_l = wr + i16 * 16 + r0 + (((e & 3) >= 2) ? 8 : 0);
                int col_l = wc + j * 16 + c0 + ((e >= 4) ? 8 : 0);   // even
                float v0 = acc[i16][j].x[e];
                float v1 = acc[i16][j].x[e + 1];
                float o0, o1;
                if (z < 2) {
                    float cc = fcs[row_l * 64 + (col_l >> 1)];
                    float ss = fsn[row_l * 64 + (col_l >> 1)];
                    o0 = v0 * cc - v1 * ss;
                    o1 = v0 * ss + v1 * cc;
                } else {
                    o0 = v0; o1 = v1;
                }
                *(__half2*)&dst[(size_t)(bm + row_l) * DIMSZ + bn + col_l] =
                    __floats2half2_rn(o0, o1);
            }
        }
    }
}

// ---------------------------------------------------------------------------
// Output GEMM: fp32 store to d_out. (Profiled: 4th launch.)
// ---------------------------------------------------------------------------
__global__ __launch_bounds__(256, 2) void gemm_out(float* __restrict__ C)
{
    extern __shared__ __half smh[];
    const int tid = threadIdx.x;
    const int w   = tid >> 5;
    const int bm  = blockIdx.x * 128;
    const int bn  = blockIdx.y * 128;
    const int wr  = (w >> 1) * 32;
    const int wc  = (w & 1) * 64;

    wmma::fragment<wmma::accumulator, 16, 16, 16, float> acc[2][4];
    gemm_mainloop(g_oh, g_wh + (size_t)3 * DIMSZ * DIMSZ, smh, acc, bm, bn, wr, wc, tid);

#pragma unroll
    for (int i = 0; i < 2; i++)
#pragma unroll
        for (int j = 0; j < 4; j++)
            wmma::store_matrix_sync(C + (size_t)(bm + wr + i * 16) * GN + bn + wc + j * 16,
                                    acc[i][j], GN, wmma::mem_row_major);
}

// ---------------------------------------------------------------------------
// Flash attention v6 (unchanged from R13, proven): fp16 datapath, q-tile 64,
// k-tile 64, double-buffered K/V, register O accumulator + softmax state.
// ---------------------------------------------------------------------------
#define BKT 64
#define LDQH2 136   // halves per row (128+8)
#define LDS_S 68    // fp32 scores (64+4)
#define LDPH 72     // fp16 P (64+8)
#define FLASH_HALVES (5 * 64 * LDQH2)
#define FLASH_SMEM_BYTES (FLASH_HALVES * 2 + (64 * LDS_S + 128) * 4 + 64 * LDPH * 2)

__global__ __launch_bounds__(256, 2) void flash_attn()
{
    extern __shared__ __half smh[];
    __half* Qs = smh;                        // 64 x LDQH2
    __half* Ks = Qs + 64 * LDQH2;            // 2 x 64 x LDQH2
    __half* Vs = Ks + 2 * 64 * LDQH2;        // 2 x 64 x LDQH2
    float*  Ss = (float*)(Vs + 2 * 64 * LDQH2);   // 64 x LDS_S fp32
    float*  lrow = Ss + 64 * LDS_S;
    float*  arow = lrow + 64;
    __half* Ps = (__half*)(arow + 64);       // 64 x LDPH fp16

    const int qb   = (gridDim.x - 1) - blockIdx.x;
    const int h    = blockIdx.y;
    const int tid  = threadIdx.x;
    const int w    = tid >> 5;
    const int lane = tid & 31;
    const float scale = 0.08838834764831845f;  // 1/sqrt(128)

    const __half* Qg = g_qh + (size_t)qb * 64 * DIMSZ + h * HDIM;
    const __half* Kh = g_kh + (size_t)h * HDIM;
    const __half* Vh = g_vh + (size_t)h * HDIM;

    const int owr = (w >> 2) * 32;
    const int owc = (w & 3) * 32;
    wmma::fragment<wmma::accumulator, 16, 16, 16, float> oacc[2][2];
#pragma unroll
    for (int i = 0; i < 2; i++)
#pragma unroll
        for (int j = 0; j < 2; j++) wmma::fill_fragment(oacc[i][j], 0.0f);

    const int srow = tid >> 2;
    const int ssub = tid & 3;
    float m_state = -1e30f;
    float l_state = 0.0f;

#pragma unroll
    for (int i = 0; i < 4; i++) {
        int idx = tid + i * 256;
        int r = idx >> 4, c8 = (idx & 15) << 3;
        cp16(&Qs[r * LDQH2 + c8], Qg + (size_t)r * DIMSZ + c8);
        cp16(&Ks[r * LDQH2 + c8], Kh + (size_t)r * DIMSZ + c8);
        cp16(&Vs[r * LDQH2 + c8], Vh + (size_t)r * DIMSZ + c8);
    }
    CP_COMMIT();

    const int ntiles = qb + 1;

    for (int kt = 0; kt < ntiles; kt++) {
        const int buf = kt & 1;

        if (kt + 1 < ntiles) {
            __half* Kn = Ks + (buf ^ 1) * 64 * LDQH2;
            __half* Vn = Vs + (buf ^ 1) * 64 * LDQH2;
            const __half* Kg = Kh + (size_t)(kt + 1) * 64 * DIMSZ;
            const __half* Vg = Vh + (size_t)(kt + 1) * 64 * DIMSZ;
#pragma unroll
            for (int i = 0; i < 4; i++) {
                int idx = tid + i * 256;
                int r = idx >> 4, c8 = (idx & 15) << 3;
                cp16(&Kn[r * LDQH2 + c8], Kg + (size_t)r * DIMSZ + c8);
                cp16(&Vn[r * LDQH2 + c8], Vg + (size_t)r * DIMSZ + c8);
            }
            CP_COMMIT();
            CP_WAITG(1);
        } else {
            CP_WAITG(0);
        }
        __syncthreads();

        const __half* Kc = Ks + buf * 64 * LDQH2;
        const __half* Vc = Vs + buf * 64 * LDQH2;

        // S = scale * Q @ K^T : warp grid 4x2, each warp 16 rows x 32 cols
        {
            const int wr = (w >> 1) * 16;
            const int wc = (w & 1) * 32;
            wmma::fragment<wmma::accumulator, 16, 16, 16, float> c[2];
            wmma::fill_fragment(c[0], 0.0f);
            wmma::fill_fragment(c[1], 0.0f);
#pragma unroll
            for (int ks = 0; ks < 8; ks++) {
                wmma::fragment<wmma::matrix_a, 16, 16, 16, __half, wmma::row_major> a;
                wmma::load_matrix_sync(a, &Qs[wr * LDQH2 + ks * 16], LDQH2);
#pragma unroll
                for (int j = 0; j < 2; j++) {
                    wmma::fragment<wmma::matrix_b, 16, 16, 16, __half, wmma::col_major> b;
                    wmma::load_matrix_sync(b, &Kc[(wc + j * 16) * LDQH2 + ks * 16], LDQH2);
                    wmma::mma_sync(c[j], a, b, c[j]);
                }
            }
#pragma unroll
            for (int j = 0; j < 2; j++) {
#pragma unroll
                for (int t = 0; t < c[j].num_elements; t++) c[j].x[t] *= scale;
                wmma::store_matrix_sync(&Ss[wr * LDS_S + wc + j * 16], c[j], LDS_S,
                                        wmma::mem_row_major);
            }
        }
        __syncthreads();

        // Online softmax: 4 threads/row, 16 cols each; P -> fp16 Ps.
        {
            int lim = qb * 64 + srow - kt * 64;
            int smax = lim + 1;
            if (smax > BKT) smax = BKT;
            if (smax < 0)   smax = 0;
            float mloc = -1e30f;
            int c0 = ssub * 16;
#pragma unroll
            for (int c = 0; c < 16; c++) {
                int cc = c0 + c;
                if (cc < smax) mloc = fmaxf(mloc, Ss[srow * LDS_S + cc]);
            }
#pragma unroll
            for (int o = 1; o < 4; o <<= 1)
                mloc = fmaxf(mloc, __shfl_xor_sync(0xffffffffu, mloc, o));
            float mn = fmaxf(m_state, mloc);
            float alpha = __expf(m_state - mn);
            float lsum = 0.0f;
#pragma unroll
            for (int c = 0; c < 16; c += 2) {
                int cc = c0 + c;
                float p0 = (cc < smax)     ? __expf(Ss[srow * LDS_S + cc] - mn)     : 0.0f;
                float p1 = (cc + 1 < smax) ? __expf(Ss[srow * LDS_S + cc + 1] - mn) : 0.0f;
                *(__half2*)&Ps[srow * LDPH + cc] = __floats2half2_rn(p0, p1);
                lsum += p0 + p1;
            }
#pragma unroll
            for (int o = 1; o < 4; o <<= 1)
                lsum += __shfl_xor_sync(0xffffffffu, lsum, o);
            l_state = l_state * alpha + lsum;
            m_state = mn;
            if (ssub == 0) arow[srow] = alpha;
        }
        __syncthreads();

        // Rescale O accumulator in registers
        {
            const int r0 = lane >> 2;
#pragma unroll
            for (int i = 0; i < 2; i++) {
                float a0 = arow[owr + i * 16 + r0];
                float a1 = arow[owr + i * 16 + r0 + 8];
#pragma unroll
                for (int j = 0; j < 2; j++)
#pragma unroll
                    for (int e = 0; e < 8; e++)
                        oacc[i][j].x[e] *= ((e & 3) >= 2) ? a1 : a0;
            }
        }

        // O += P @ V : warp grid 2x4, each warp 32x32, 4 k-steps of 16
        {
#pragma unroll
            for (int ks = 0; ks < 4; ks++) {
                wmma::fragment<wmma::matrix_a, 16, 16, 16, __half, wmma::row_major> a[2];
                wmma::fragment<wmma::matrix_b, 16, 16, 16, __half, wmma::row_major> b[2];
#pragma unroll
                for (int i = 0; i < 2; i++)
                    wmma::load_matrix_sync(a[i], &Ps[(owr + i * 16) * LDPH + ks * 16], LDPH);
#pragma unroll
                for (int j = 0; j < 2; j++)
                    wmma::load_matrix_sync(b[j], &Vc[(ks * 16) * LDQH2 + owc + j * 16], LDQH2);
#pragma unroll
                for (int i = 0; i < 2; i++)
#pragma unroll
                    for (int j = 0; j < 2; j++)
                        wmma::mma_sync(oacc[i][j], a[i], b[j], oacc[i][j]);
            }
        }
        __syncthreads();
    }

    if (ssub == 0) lrow[srow] = l_state;
    __syncthreads();

    __half* Og = g_oh + (size_t)qb * 64 * DIMSZ + h * HDIM;
    {
        const int r0 = lane >> 2;
        const int c0 = (lane & 3) * 2;
#pragma unroll
        for (int i = 0; i < 2; i++) {
            float inv0 = 1.0f / lrow[owr + i * 16 + r0];
            float inv1 = 1.0f / lrow[owr + i * 16 + r0 + 8];
#pragma unroll
            for (int j = 0; j < 2; j++) {
#pragma unroll
                for (int e = 0; e < 8; e++) {
                    float v = oacc[i][j].x[e] * (((e & 3) >= 2) ? inv1 : inv0);
                    int row = owr + i * 16 + r0 + (((e & 3) >= 2) ? 8 : 0);
                    int col = owc + j * 16 + c0 + (e & 1) + ((e >= 4) ? 8 : 0);
                    Og[(size_t)row * DIMSZ + col] = __float2half_rn(v);
                }
            }
        }
    }
}

// ---------------------------------------------------------------------------
extern "C" void kernel_launch(void* const* d_in, const int* in_sizes, int n_in,
                              void* d_out, int out_size)
{
    const float* x  = (const float*)d_in[0];
    const float* wq = (const float*)d_in[1];
    const float* wk = (const float*)d_in[2];
    const float* wv = (const float*)d_in[3];
    const float* wo = (const float*)d_in[4];
    const float* fc = (const float*)d_in[5];
    const float* fs = (const float*)d_in[6];
    float* out = (float*)d_out;

    cudaFuncSetAttribute(gemm_qkv, cudaFuncAttributeMaxDynamicSharedMemorySize,
                         GEMM_SMEM_BYTES);
    cudaFuncSetAttribute(gemm_out, cudaFuncAttributeMaxDynamicSharedMemorySize,
                         GEMM_SMEM_BYTES);
    cudaFuncSetAttribute(flash_attn, cudaFuncAttributeMaxDynamicSharedMemorySize,
                         FLASH_SMEM_BYTES);

    // 1: fused fp16 conversion (x + 4 weights)
    dim3 cgrid((W4 + 255) / 256, 1, 5);
    cvt_all<<<cgrid, 256>>>((const float4*)x, (const float4*)wq, (const float4*)wk,
                            (const float4*)wv, (const float4*)wo);

    // 2: QKV projections with FUSED rope + fp16 epilogue (no rope kernel,
    //    no fp32 QKV round-trip)
    dim3 qkv_grid(GM / 128, GN / 128, 3);
    gemm_qkv<<<qkv_grid, 256, GEMM_SMEM_BYTES>>>(fc, fs);

    // 3: flash attention v6
    flash_attn<<<dim3(SEQ / 64, NHEAD), 256, FLASH_SMEM_BYTES>>>();

    // 4: output projection (4th launch -> ncu profiles the fp16 GEMM)
    dim3 ogrid(GM / 128, GN / 128);
    gemm_out<<<ogrid, 256, GEMM_SMEM_BYTES>>>(out);
}